// round 14
// baseline (speedup 1.0000x reference)
#include <cuda_runtime.h>
#include <cuda_bf16.h>
#include <cstdint>
#include <math.h>

// Problem dims
#define B_    4
#define S_    2048
#define E_    2048
#define H_    16
#define HD_   128
#define M_    8192
#define NTOK  (B_ * S_)      // 8192
#define QKVLD (3 * E_)       // 6144

// ============================ PTX helpers (arch-generic, sm_80+) ============
__device__ __forceinline__ uint32_t smem_to_u32(const void* p) {
    uint32_t a;
    asm("{ .reg .u64 t; cvta.to.shared.u64 t, %1; cvt.u32.u64 %0, t; }" : "=r"(a) : "l"(p));
    return a;
}
__device__ __forceinline__ void cpa16(uint32_t s, const void* g) {
    asm volatile("cp.async.cg.shared.global [%0], [%1], 16;" :: "r"(s), "l"(g));
}
#define CPA_COMMIT()  asm volatile("cp.async.commit_group;" ::: "memory")
#define CPA_WAIT_1()  asm volatile("cp.async.wait_group 1;" ::: "memory")
#define CPA_WAIT_0()  asm volatile("cp.async.wait_group 0;" ::: "memory")

#define LDSM_X4(r0, r1, r2, r3, addr) \
    asm volatile("ldmatrix.sync.aligned.m8n8.x4.shared.b16 {%0,%1,%2,%3}, [%4];" \
        : "=r"(r0), "=r"(r1), "=r"(r2), "=r"(r3) : "r"(addr))
#define LDSM_X2(r0, r1, addr) \
    asm volatile("ldmatrix.sync.aligned.m8n8.x2.shared.b16 {%0,%1}, [%2];" \
        : "=r"(r0), "=r"(r1) : "r"(addr))
#define MMA_16816(c0, c1, c2, c3, a0, a1, a2, a3, b0, b1) \
    asm volatile("mma.sync.aligned.m16n8k16.row.col.f32.bf16.bf16.f32 " \
        "{%0,%1,%2,%3}, {%4,%5,%6,%7}, {%8,%9}, {%0,%1,%2,%3};" \
        : "+f"(c0), "+f"(c1), "+f"(c2), "+f"(c3) \
        : "r"(a0), "r"(a1), "r"(a2), "r"(a3), "r"(b0), "r"(b1))

// ============================ scratch =======================================
__device__ float          g_scores[(size_t)B_ * H_ * S_ * S_];  //   1 GB fp32
__device__ float          g_x2[(size_t)NTOK * E_];              //  64 MB fp32
__device__ float          g_vf[(size_t)NTOK * E_];              //  64 MB fp32 (V)
__device__ __nv_bfloat16  g_q3[(size_t)NTOK * H_ * 384];        // 100 MB (Q split)
__device__ __nv_bfloat16  g_k3[(size_t)NTOK * H_ * 384];        // 100 MB (K split)
__device__ __nv_bfloat16  g_v3[(size_t)B_ * H_ * HD_ * 3 * S_]; // 100 MB (V^T split)
__device__ __nv_bfloat16  g_wa3[(size_t)B_ * H_ * S_ * 3 * S_]; // 1.6 GB (softmax W split)
__device__ __nv_bfloat16  g_act3a[(size_t)NTOK * 3 * E_];       // 100 MB (split act)
__device__ __nv_bfloat16  g_act3b[(size_t)NTOK * 3 * M_];       // 402 MB (split ff)
__device__ __nv_bfloat16  g_w3[(size_t)50331648];               // 100 MB (split weights)

// ============================ math helpers ==================================
__device__ __forceinline__ float gelu_new(float x)
{
    float u = 0.7978845608028654f * (x + 0.044715f * x * x * x);
    return 0.5f * x * (1.0f + tanhf(u));
}

// A-side split: [hi | lo | hi] segments of width `seg` at base+col
__device__ __forceinline__ void store_split2(__nv_bfloat16* base, int col, int seg, float a, float b)
{
    __nv_bfloat16 ha = __float2bfloat16(a), hb = __float2bfloat16(b);
    __nv_bfloat16 la = __float2bfloat16(a - __bfloat162float(ha));
    __nv_bfloat16 lb = __float2bfloat16(b - __bfloat162float(hb));
    __nv_bfloat162 hh; hh.x = ha; hh.y = hb;
    __nv_bfloat162 ll; ll.x = la; ll.y = lb;
    *(__nv_bfloat162*)(base + col)           = hh;
    *(__nv_bfloat162*)(base + seg + col)     = ll;
    *(__nv_bfloat162*)(base + 2 * seg + col) = hh;
}
// B-side split: [hi | hi | lo]
__device__ __forceinline__ void store_split2b(__nv_bfloat16* base, int col, int seg, float a, float b)
{
    __nv_bfloat16 ha = __float2bfloat16(a), hb = __float2bfloat16(b);
    __nv_bfloat16 la = __float2bfloat16(a - __bfloat162float(ha));
    __nv_bfloat16 lb = __float2bfloat16(b - __bfloat162float(hb));
    __nv_bfloat162 hh; hh.x = ha; hh.y = hb;
    __nv_bfloat162 ll; ll.x = la; ll.y = lb;
    *(__nv_bfloat162*)(base + col)           = hh;
    *(__nv_bfloat162*)(base + seg + col)     = hh;
    *(__nv_bfloat162*)(base + 2 * seg + col) = ll;
}

// ---------------- LayerNorm -> split bf16 [hi|lo|hi], row stride 6144 -------
__global__ __launch_bounds__(256)
void ln_split(const float* __restrict__ x, const float* __restrict__ gam,
              const float* __restrict__ bet, __nv_bfloat16* __restrict__ out3)
{
    const int row = blockIdx.x;
    const int t = threadIdx.x;
    const float4* x4 = reinterpret_cast<const float4*>(x + (size_t)row * E_);
    float4 v0 = x4[t];
    float4 v1 = x4[t + 256];

    __shared__ float sh[256];
    float s = v0.x + v0.y + v0.z + v0.w + v1.x + v1.y + v1.z + v1.w;
    sh[t] = s;
    __syncthreads();
    #pragma unroll
    for (int o = 128; o > 0; o >>= 1) {
        if (t < o) sh[t] += sh[t + o];
        __syncthreads();
    }
    const float mu = sh[0] * (1.0f / (float)E_);
    __syncthreads();

    float d, sq = 0.f;
    d = v0.x - mu; sq += d * d;  d = v0.y - mu; sq += d * d;
    d = v0.z - mu; sq += d * d;  d = v0.w - mu; sq += d * d;
    d = v1.x - mu; sq += d * d;  d = v1.y - mu; sq += d * d;
    d = v1.z - mu; sq += d * d;  d = v1.w - mu; sq += d * d;
    sh[t] = sq;
    __syncthreads();
    #pragma unroll
    for (int o = 128; o > 0; o >>= 1) {
        if (t < o) sh[t] += sh[t + o];
        __syncthreads();
    }
    const float var = sh[0] * (1.0f / (float)E_);
    const float inv = rsqrtf(var + 1e-5f);

    const float4* g4 = reinterpret_cast<const float4*>(gam);
    const float4* b4 = reinterpret_cast<const float4*>(bet);
    float4 gg0 = g4[t], gg1 = g4[t + 256];
    float4 bb0 = b4[t], bb1 = b4[t + 256];

    float o0x = (v0.x - mu) * inv * gg0.x + bb0.x;
    float o0y = (v0.y - mu) * inv * gg0.y + bb0.y;
    float o0z = (v0.z - mu) * inv * gg0.z + bb0.z;
    float o0w = (v0.w - mu) * inv * gg0.w + bb0.w;
    float o1x = (v1.x - mu) * inv * gg1.x + bb1.x;
    float o1y = (v1.y - mu) * inv * gg1.y + bb1.y;
    float o1z = (v1.z - mu) * inv * gg1.z + bb1.z;
    float o1w = (v1.w - mu) * inv * gg1.w + bb1.w;

    __nv_bfloat16* o = out3 + (size_t)row * (3 * E_);
    store_split2(o, 4 * t,            E_, o0x, o0y);
    store_split2(o, 4 * t + 2,        E_, o0z, o0w);
    store_split2(o, 1024 + 4 * t,     E_, o1x, o1y);
    store_split2(o, 1024 + 4 * t + 2, E_, o1z, o1w);
}

// ---------------- weight split+transpose: W[K,N] fp32 -> out[N, 3K] bf16 ----
// segments [hi | hi | lo]
__global__ __launch_bounds__(256)
void split_wt(const float* __restrict__ W, int K, int N, __nv_bfloat16* __restrict__ out)
{
    __shared__ float tile[32][33];
    const int n0 = blockIdx.x * 32, k0 = blockIdx.y * 32;
    const int tx = threadIdx.x & 31, ty = threadIdx.x >> 5;  // ty 0..7
    #pragma unroll
    for (int i = 0; i < 4; i++)
        tile[ty + i * 8][tx] = W[(size_t)(k0 + ty + i * 8) * N + n0 + tx];
    __syncthreads();
    const size_t ld3 = (size_t)3 * K;
    #pragma unroll
    for (int i = 0; i < 4; i++) {
        int n = n0 + ty + i * 8;
        float v = tile[tx][ty + i * 8];
        __nv_bfloat16 hv = __float2bfloat16(v);
        __nv_bfloat16 lv = __float2bfloat16(v - __bfloat162float(hv));
        __nv_bfloat16* o = out + (size_t)n * ld3 + k0 + tx;
        o[0]     = hv;
        o[K]     = hv;
        o[2 * K] = lv;
    }
}

// ---------------- V split+transpose: per head, vf[s, h*128+d] -> v3[d, 3*2048]
__global__ __launch_bounds__(256)
void split_vt(const float* __restrict__ vf, __nv_bfloat16* __restrict__ v3)
{
    __shared__ float tile[32][33];
    const int z = blockIdx.z;                 // head index b*16+h
    const int b = z >> 4, h = z & 15;
    const int n0 = blockIdx.x * 32;           // d
    const int k0 = blockIdx.y * 32;           // s
    const int tx = threadIdx.x & 31, ty = threadIdx.x >> 5;
    const float* Wb = vf + ((size_t)b * S_) * E_ + h * HD_;
    #pragma unroll
    for (int i = 0; i < 4; i++)
        tile[ty + i * 8][tx] = Wb[(size_t)(k0 + ty + i * 8) * E_ + n0 + tx];
    __syncthreads();
    #pragma unroll
    for (int i = 0; i < 4; i++) {
        int n = n0 + ty + i * 8;
        float v = tile[tx][ty + i * 8];
        __nv_bfloat16 hv = __float2bfloat16(v);
        __nv_bfloat16 lv = __float2bfloat16(v - __bfloat162float(hv));
        __nv_bfloat16* o = v3 + ((size_t)z * HD_ + n) * (3 * S_) + k0 + tx;
        o[0]        = hv;
        o[S_]       = hv;
        o[2 * S_]   = lv;
    }
}

// ---------------- HMMA bf16 GEMM, 3-stage single-sync pipeline ---------------
// CTA 128x128, BK=32, 8 warps of 64x32, cp.async 3-stage ring (1 sync/chunk).
// EPI: 2 = gelu(+bias) -> split bf16 ; 3 = +bias+res -> fp32 ; 4 = qkv special
#define BKC 32
#define PADK 40                      // smem row bf16 (32 data + 8 pad)
#define TSTG (128 * PADK * 2)        // 10240 B per tile stage
#define SMEM3 (6 * TSTG)             // 3 stages x (A + B) = 61440 B

#define ATT_SCALE 0.08838834764831845f

template<int EPI>
__global__ __launch_bounds__(256, 2)
void gemm_bf3(const __nv_bfloat16* __restrict__ A, int lda,
              const __nv_bfloat16* __restrict__ Bw, int ldb, int K,
              float* __restrict__ Cf, int ldc,
              const float* __restrict__ bias,
              const float* __restrict__ res, int ldres,
              __nv_bfloat16* __restrict__ Cs, int ldcs, int koff,
              __nv_bfloat16* __restrict__ q3, __nv_bfloat16* __restrict__ k3,
              float* __restrict__ vf)
{
    extern __shared__ char smem[];
    const uint32_t ASM = smem_to_u32(smem);       // 3 A stages
    const uint32_t BSM = ASM + 3 * TSTG;          // 3 B stages

    const int t = threadIdx.x;
    const int wid = t >> 5, lane = t & 31;
    const int wm = (wid >> 2) * 64;
    const int wn = (wid & 3) * 32;
    const int row0 = blockIdx.y * 128;
    const int col0 = blockIdx.x * 128;

    const int gr = t >> 2;
    const int gc = (t & 3) * 8;

    const __nv_bfloat16* Ag = A  + (size_t)(row0 + gr) * lda + gc;
    const __nv_bfloat16* Bg = Bw + (size_t)(col0 + gr) * ldb + gc;
    const size_t ldA64 = (size_t)64 * lda;
    const size_t ldB64 = (size_t)64 * ldb;

    const uint32_t ldo = (uint32_t)(gr * PADK + gc) * 2;
    const uint32_t ldo1 = (uint32_t)((gr + 64) * PADK + gc) * 2;

    float acc[4][4][4];
    #pragma unroll
    for (int i = 0; i < 4; i++)
        #pragma unroll
        for (int j = 0; j < 4; j++)
            #pragma unroll
            for (int q = 0; q < 4; q++) acc[i][j][q] = 0.f;

    const int nchunks = K / BKC;

    #pragma unroll
    for (int c = 0; c < 2; c++) {
        const int kc = c * BKC;
        cpa16(ASM + c * TSTG + ldo,  Ag + kc);
        cpa16(ASM + c * TSTG + ldo1, Ag + ldA64 + kc);
        cpa16(BSM + c * TSTG + ldo,  Bg + kc);
        cpa16(BSM + c * TSTG + ldo1, Bg + ldB64 + kc);
        CPA_COMMIT();
    }

    const int al = lane & 15;
    const uint32_t a_base = ASM + (uint32_t)((wm + (lane & 15)) * PADK + (lane >> 4) * 8) * 2;
    const uint32_t b_base = BSM + (uint32_t)((wn + (al & 7)) * PADK + (al >> 3) * 8) * 2;

    int st_c = 0, st_p = 2;
    for (int c = 0; c < nchunks; c++) {
        if (c + 2 < nchunks) CPA_WAIT_1(); else CPA_WAIT_0();
        __syncthreads();

        if (c + 2 < nchunks) {
            const int kc = (c + 2) * BKC;
            cpa16(ASM + st_p * TSTG + ldo,  Ag + kc);
            cpa16(ASM + st_p * TSTG + ldo1, Ag + ldA64 + kc);
            cpa16(BSM + st_p * TSTG + ldo,  Bg + kc);
            cpa16(BSM + st_p * TSTG + ldo1, Bg + ldB64 + kc);
            CPA_COMMIT();
        }

        const uint32_t ab = a_base + st_c * TSTG;
        const uint32_t bb = b_base + st_c * TSTG;
        #pragma unroll
        for (int kk = 0; kk < 2; kk++) {
            uint32_t a[4][4], b[4][2];
            #pragma unroll
            for (int mt = 0; mt < 4; mt++)
                LDSM_X4(a[mt][0], a[mt][1], a[mt][2], a[mt][3],
                        ab + (mt * 16 * PADK + kk * 16) * 2);
            #pragma unroll
            for (int nt = 0; nt < 4; nt++)
                LDSM_X2(b[nt][0], b[nt][1],
                        bb + (nt * 8 * PADK + kk * 16) * 2);
            #pragma unroll
            for (int mt = 0; mt < 4; mt++)
                #pragma unroll
                for (int nt = 0; nt < 4; nt++)
                    MMA_16816(acc[mt][nt][0], acc[mt][nt][1], acc[mt][nt][2], acc[mt][nt][3],
                              a[mt][0], a[mt][1], a[mt][2], a[mt][3],
                              b[nt][0], b[nt][1]);
        }
        st_c = (st_c == 2) ? 0 : st_c + 1;
        st_p = (st_p == 2) ? 0 : st_p + 1;
    }

    // ---- epilogue ----
    const int er = lane >> 2;
    const int ec = (lane & 3) * 2;
    #pragma unroll
    for (int mt = 0; mt < 4; mt++) {
        #pragma unroll
        for (int nt = 0; nt < 4; nt++) {
            const int r  = row0 + wm + mt * 16 + er;
            const int ci = col0 + wn + nt * 8 + ec;
            float b0 = bias[ci], b1 = bias[ci + 1];
            float v0 = acc[mt][nt][0] + b0, v1 = acc[mt][nt][1] + b1;
            float v2 = acc[mt][nt][2] + b0, v3 = acc[mt][nt][3] + b1;
            if (EPI == 2) {
                __nv_bfloat16* base0 = Cs + (size_t)r * ldcs;
                __nv_bfloat16* base1 = Cs + (size_t)(r + 8) * ldcs;
                store_split2(base0, ci, koff, gelu_new(v0), gelu_new(v1));
                store_split2(base1, ci, koff, gelu_new(v2), gelu_new(v3));
            } else if (EPI == 3) {
                float2 r0 = *(const float2*)(res + (size_t)r * ldres + ci);
                float2 r1 = *(const float2*)(res + (size_t)(r + 8) * ldres + ci);
                v0 += r0.x; v1 += r0.y; v2 += r1.x; v3 += r1.y;
                float2 w0; w0.x = v0; w0.y = v1;
                float2 w1; w1.x = v2; w1.y = v3;
                *(float2*)(Cf + (size_t)r * ldc + ci)       = w0;
                *(float2*)(Cf + (size_t)(r + 8) * ldc + ci) = w1;
            } else {  // EPI == 4: qkv — q->q3 scaled split, k->k3 split, v->vf fp32
                if (ci < E_) {
                    const int h = ci >> 7, dd = ci & 127;
                    store_split2(q3 + (size_t)r * (H_ * 384) + h * 384, dd, HD_,
                                 v0 * ATT_SCALE, v1 * ATT_SCALE);
                    store_split2(q3 + (size_t)(r + 8) * (H_ * 384) + h * 384, dd, HD_,
                                 v2 * ATT_SCALE, v3 * ATT_SCALE);
                } else if (ci < 2 * E_) {
                    const int c2 = ci - E_;
                    const int h = c2 >> 7, dd = c2 & 127;
                    store_split2b(k3 + (size_t)r * (H_ * 384) + h * 384, dd, HD_, v0, v1);
                    store_split2b(k3 + (size_t)(r + 8) * (H_ * 384) + h * 384, dd, HD_, v2, v3);
                } else {
                    const int c2 = ci - 2 * E_;
                    float2 w0; w0.x = v0; w0.y = v1;
                    float2 w1; w1.x = v2; w1.y = v3;
                    *(float2*)(vf + (size_t)r * E_ + c2)       = w0;
                    *(float2*)(vf + (size_t)(r + 8) * E_ + c2) = w1;
                }
            }
        }
    }
}

// ---------------- scores = Qs @ Ks^T (HMMA, split-3, 3-stage pipeline) -------
__global__ __launch_bounds__(256, 2)
void scores_mma(const __nv_bfloat16* __restrict__ q3, const __nv_bfloat16* __restrict__ k3,
                float* __restrict__ scores)
{
    const int bn = blockIdx.x, bm = blockIdx.y;
    if (bn > bm) return;
    const int z = blockIdx.z;
    const int b = z >> 4, h = z & 15;
    const int row0 = bm * 128, col0 = bn * 128;
    const int lda = H_ * 384;

    extern __shared__ char smem[];
    const uint32_t ASM = smem_to_u32(smem);
    const uint32_t BSM = ASM + 3 * TSTG;

    const int t = threadIdx.x;
    const int wid = t >> 5, lane = t & 31;
    const int wm = (wid >> 2) * 64;
    const int wn = (wid & 3) * 32;
    const int gr = t >> 2;
    const int gc = (t & 3) * 8;

    const __nv_bfloat16* Ag = q3 + (size_t)((b << 11) + row0 + gr) * lda + h * 384 + gc;
    const __nv_bfloat16* Bg = k3 + (size_t)((b << 11) + col0 + gr) * lda + h * 384 + gc;
    const size_t ld64 = (size_t)64 * lda;

    const uint32_t ldo = (uint32_t)(gr * PADK + gc) * 2;
    const uint32_t ldo1 = (uint32_t)((gr + 64) * PADK + gc) * 2;

    float acc[4][4][4];
    #pragma unroll
    for (int i = 0; i < 4; i++)
        #pragma unroll
        for (int j = 0; j < 4; j++)
            #pragma unroll
            for (int q = 0; q < 4; q++) acc[i][j][q] = 0.f;

    const int nchunks = 384 / BKC;   // 12

    #pragma unroll
    for (int c = 0; c < 2; c++) {
        const int kc = c * BKC;
        cpa16(ASM + c * TSTG + ldo,  Ag + kc);
        cpa16(ASM + c * TSTG + ldo1, Ag + ld64 + kc);
        cpa16(BSM + c * TSTG + ldo,  Bg + kc);
        cpa16(BSM + c * TSTG + ldo1, Bg + ld64 + kc);
        CPA_COMMIT();
    }

    const int al = lane & 15;
    const uint32_t a_base = ASM + (uint32_t)((wm + (lane & 15)) * PADK + (lane >> 4) * 8) * 2;
    const uint32_t b_base = BSM + (uint32_t)((wn + (al & 7)) * PADK + (al >> 3) * 8) * 2;

    int st_c = 0, st_p = 2;
    for (int c = 0; c < nchunks; c++) {
        if (c + 2 < nchunks) CPA_WAIT_1(); else CPA_WAIT_0();
        __syncthreads();
        if (c + 2 < nchunks) {
            const int kc = (c + 2) * BKC;
            cpa16(ASM + st_p * TSTG + ldo,  Ag + kc);
            cpa16(ASM + st_p * TSTG + ldo1, Ag + ld64 + kc);
            cpa16(BSM + st_p * TSTG + ldo,  Bg + kc);
            cpa16(BSM + st_p * TSTG + ldo1, Bg + ld64 + kc);
            CPA_COMMIT();
        }
        const uint32_t ab = a_base + st_c * TSTG;
        const uint32_t bb = b_base + st_c * TSTG;
        #pragma unroll
        for (int kk = 0; kk < 2; kk++) {
            uint32_t a[4][4], bfr[4][2];
            #pragma unroll
            for (int mt = 0; mt < 4; mt++)
                LDSM_X4(a[mt][0], a[mt][1], a[mt][2], a[mt][3],
                        ab + (mt * 16 * PADK + kk * 16) * 2);
            #pragma unroll
            for (int nt = 0; nt < 4; nt++)
                LDSM_X2(bfr[nt][0], bfr[nt][1],
                        bb + (nt * 8 * PADK + kk * 16) * 2);
            #pragma unroll
            for (int mt = 0; mt < 4; mt++)
                #pragma unroll
                for (int nt = 0; nt < 4; nt++)
                    MMA_16816(acc[mt][nt][0], acc[mt][nt][1], acc[mt][nt][2], acc[mt][nt][3],
                              a[mt][0], a[mt][1], a[mt][2], a[mt][3],
                              bfr[nt][0], bfr[nt][1]);
        }
        st_c = (st_c == 2) ? 0 : st_c + 1;
        st_p = (st_p == 2) ? 0 : st_p + 1;
    }

    float* sbuf = scores + (size_t)z * S_ * S_;
    const int er = lane >> 2;
    const int ec = (lane & 3) * 2;
    #pragma unroll
    for (int mt = 0; mt < 4; mt++) {
        #pragma unroll
        for (int nt = 0; nt < 4; nt++) {
            const int r  = row0 + wm + mt * 16 + er;
            const int ci = col0 + wn + nt * 8 + ec;
            float2 w0; w0.x = acc[mt][nt][0]; w0.y = acc[mt][nt][1];
            float2 w1; w1.x = acc[mt][nt][2]; w1.y = acc[mt][nt][3];
            *(float2*)(sbuf + (size_t)r * S_ + ci)       = w0;
            *(float2*)(sbuf + (size_t)(r + 8) * S_ + ci) = w1;
        }
    }
}

// ---------------- causal softmax -> split bf16 W [hi|lo|hi] ------------------
__global__ __launch_bounds__(256)
void softmax_causal(const float* __restrict__ scores, __nv_bfloat16* __restrict__ wa3)
{
    const int q = blockIdx.x;
    const int z = blockIdx.y;
    const float* row = scores + (size_t)z * S_ * S_ + (size_t)q * S_;
    const int len = q + 1;
    const int kend = ((q >> 7) + 1) << 7;
    const int t = threadIdx.x;

    float r[8];
    float mx = -1e30f;
    #pragma unroll
    for (int i = 0; i < 8; i++) {
        const int k = t + i * 256;
        r[i] = (k < len) ? row[k] : -1e30f;
        mx = fmaxf(mx, r[i]);
    }
    __shared__ float sh[256];
    sh[t] = mx;
    __syncthreads();
    #pragma unroll
    for (int o = 128; o > 0; o >>= 1) {
        if (t < o) sh[t] = fmaxf(sh[t], sh[t + o]);
        __syncthreads();
    }
    mx = sh[0];
    __syncthreads();

    float sum = 0.f;
    #pragma unroll
    for (int i = 0; i < 8; i++) {
        const int k = t + i * 256;
        if (k < len) { r[i] = __expf(r[i] - mx); sum += r[i]; }
        else r[i] = 0.f;
    }
    sh[t] = sum;
    __syncthreads();
    #pragma unroll
    for (int o = 128; o > 0; o >>= 1) {
        if (t < o) sh[t] += sh[t + o];
        __syncthreads();
    }
    const float inv = 1.0f / sh[0];

    __nv_bfloat16* wrow = wa3 + ((size_t)z * S_ + q) * (3 * S_);
    #pragma unroll
    for (int i = 0; i < 8; i++) {
        const int k = t + i * 256;
        if (k < kend) {
            float w = (k < len) ? r[i] * inv : 0.f;
            __nv_bfloat16 hi = __float2bfloat16(w);
            __nv_bfloat16 lo = __float2bfloat16(w - __bfloat162float(hi));
            wrow[k]          = hi;
            wrow[S_ + k]     = lo;
            wrow[2 * S_ + k] = hi;
        }
    }
}

// ---------------- attn = W @ V (HMMA, split-3, 3-stage pipeline) -------------
__global__ __launch_bounds__(256, 2)
void av_mma(const __nv_bfloat16* __restrict__ wa3, const __nv_bfloat16* __restrict__ v3,
            __nv_bfloat16* __restrict__ act3)
{
    const int qt = blockIdx.x;
    const int z = blockIdx.y;
    const int b = z >> 4, h = z & 15;
    const int row0 = qt * 128;
    const int Kend = (qt + 1) * 128;
    const int nchunks = 3 * Kend / BKC;

    extern __shared__ char smem[];
    const uint32_t ASM = smem_to_u32(smem);
    const uint32_t BSM = ASM + 3 * TSTG;

    const int t = threadIdx.x;
    const int wid = t >> 5, lane = t & 31;
    const int wm = (wid >> 2) * 64;
    const int wn = (wid & 3) * 32;
    const int gr = t >> 2;
    const int gc = (t & 3) * 8;

    const __nv_bfloat16* Ag = wa3 + ((size_t)z * S_ + row0 + gr) * (3 * S_) + gc;
    const __nv_bfloat16* Bg = v3 + ((size_t)z * HD_ + gr) * (3 * S_) + gc;
    const size_t ldA64 = (size_t)64 * (3 * S_);
    const size_t ldB64 = (size_t)64 * (3 * S_);

    const uint32_t ldo = (uint32_t)(gr * PADK + gc) * 2;
    const uint32_t ldo1 = (uint32_t)((gr + 64) * PADK + gc) * 2;

    float acc[4][4][4];
    #pragma unroll
    for (int i = 0; i < 4; i++)
        #pragma unroll
        for (int j = 0; j < 4; j++)
            #pragma unroll
            for (int q = 0; q < 4; q++) acc[i][j][q] = 0.f;

    // load cursor: chunk -> column offset seg*2048 + kin
    int lseg = 0, lkin = 0;

    #pragma unroll
    for (int c = 0; c < 2; c++) {
        const int off = lseg * S_ + lkin;
        cpa16(ASM + c * TSTG + ldo,  Ag + off);
        cpa16(ASM + c * TSTG + ldo1, Ag + ldA64 + off);
        cpa16(BSM + c * TSTG + ldo,  Bg + off);
        cpa16(BSM + c * TSTG + ldo1, Bg + ldB64 + off);
        CPA_COMMIT();
        lkin += BKC; if (lkin == Kend) { lkin = 0; lseg++; }
    }

    const int al = lane & 15;
    const uint32_t a_base = ASM + (uint32_t)((wm + (lane & 15)) * PADK + (lane >> 4) * 8) * 2;
    const uint32_t b_base = BSM + (uint32_t)((wn + (al & 7)) * PADK + (al >> 3) * 8) * 2;

    int st_c = 0, st_p = 2;
    for (int c = 0; c < nchunks; c++) {
        if (c + 2 < nchunks) CPA_WAIT_1(); else CPA_WAIT_0();
        __syncthreads();
        if (c + 2 < nchunks) {
            const int off = lseg * S_ + lkin;
            cpa16(ASM + st_p * TSTG + ldo,  Ag + off);
            cpa16(ASM + st_p * TSTG + ldo1, Ag + ldA64 + off);
            cpa16(BSM + st_p * TSTG + ldo,  Bg + off);
            cpa16(BSM + st_p * TSTG + ldo1, Bg + ldB64 + off);
            CPA_COMMIT();
            lkin += BKC; if (lkin == Kend) { lkin = 0; lseg++; }
        }
        const uint32_t ab = a_base + st_c * TSTG;
        const uint32_t bb = b_base + st_c * TSTG;
        #pragma unroll
        for (int kk = 0; kk < 2; kk++) {
            uint32_t a[4][4], bfr[4][2];
            #pragma unroll
            for (int mt = 0; mt < 4; mt++)
                LDSM_X4(a[mt][0], a[mt][1], a[mt][2], a[mt][3],
                        ab + (mt * 16 * PADK + kk * 16) * 2);
            #pragma unroll
            for (int nt = 0; nt < 4; nt++)
                LDSM_X2(bfr[nt][0], bfr[nt][1],
                        bb + (nt * 8 * PADK + kk * 16) * 2);
            #pragma unroll
            for (int mt = 0; mt < 4; mt++)
                #pragma unroll
                for (int nt = 0; nt < 4; nt++)
                    MMA_16816(acc[mt][nt][0], acc[mt][nt][1], acc[mt][nt][2], acc[mt][nt][3],
                              a[mt][0], a[mt][1], a[mt][2], a[mt][3],
                              bfr[nt][0], bfr[nt][1]);
        }
        st_c = (st_c == 2) ? 0 : st_c + 1;
        st_p = (st_p == 2) ? 0 : st_p + 1;
    }

    // epilogue: write split activations for Wo GEMM
    const int er = lane >> 2;
    const int ec = (lane & 3) * 2;
    #pragma unroll
    for (int mt = 0; mt < 4; mt++) {
        #pragma unroll
        for (int nt = 0; nt < 4; nt++) {
            const int tok = (b << 11) + row0 + wm + mt * 16 + er;
            const int dd  = wn + nt * 8 + ec;       // 0..127
            __nv_bfloat16* op0 = act3 + (size_t)tok * (3 * E_) + h * HD_;
            __nv_bfloat16* op1 = act3 + (size_t)(tok + 8) * (3 * E_) + h * HD_;
            store_split2(op0, dd, E_, acc[mt][nt][0], acc[mt][nt][1]);
            store_split2(op1, dd, E_, acc[mt][nt][2], acc[mt][nt][3]);
        }
    }
}

// ---------------- launch -----------------------------------------------------
extern "C" void kernel_launch(void* const* d_in, const int* in_sizes, int n_in,
                              void* d_out, int out_size)
{
    const float* x     = (const float*)d_in[0];
    // d_in[1] = mask — causality handled directly
    const float* ln1_g = (const float*)d_in[2];
    const float* ln1_b = (const float*)d_in[3];
    const float* Wqkv  = (const float*)d_in[4];
    const float* bqkv  = (const float*)d_in[5];
    const float* Wo    = (const float*)d_in[6];
    const float* bo    = (const float*)d_in[7];
    const float* ln2_g = (const float*)d_in[8];
    const float* ln2_b = (const float*)d_in[9];
    const float* Wfc   = (const float*)d_in[10];
    const float* bfc   = (const float*)d_in[11];
    const float* Wp    = (const float*)d_in[12];
    const float* bp    = (const float*)d_in[13];
    float* out = (float*)d_out;

    float *scores, *x2, *vf;
    __nv_bfloat16 *act3a, *act3b, *w3, *q3, *k3, *v3, *wa3;
    cudaGetSymbolAddress((void**)&scores, g_scores);
    cudaGetSymbolAddress((void**)&x2, g_x2);
    cudaGetSymbolAddress((void**)&vf, g_vf);
    cudaGetSymbolAddress((void**)&act3a, g_act3a);
    cudaGetSymbolAddress((void**)&act3b, g_act3b);
    cudaGetSymbolAddress((void**)&w3, g_w3);
    cudaGetSymbolAddress((void**)&q3, g_q3);
    cudaGetSymbolAddress((void**)&k3, g_k3);
    cudaGetSymbolAddress((void**)&v3, g_v3);
    cudaGetSymbolAddress((void**)&wa3, g_wa3);

    cudaFuncSetAttribute(gemm_bf3<2>, cudaFuncAttributeMaxDynamicSharedMemorySize, SMEM3);
    cudaFuncSetAttribute(gemm_bf3<3>, cudaFuncAttributeMaxDynamicSharedMemorySize, SMEM3);
    cudaFuncSetAttribute(gemm_bf3<4>, cudaFuncAttributeMaxDynamicSharedMemorySize, SMEM3);
    cudaFuncSetAttribute(scores_mma, cudaFuncAttributeMaxDynamicSharedMemorySize, SMEM3);
    cudaFuncSetAttribute(av_mma, cudaFuncAttributeMaxDynamicSharedMemorySize, SMEM3);

    // 1. LN1 -> split activations [8192, 3*2048]
    ln_split<<<NTOK, 256>>>(x, ln1_g, ln1_b, act3a);
    // 2. Wqkv -> w3;  qkv GEMM -> q3 (scaled, split) / k3 (split) / vf (fp32)
    split_wt<<<dim3(QKVLD / 32, E_ / 32), 256>>>(Wqkv, E_, QKVLD, w3);
    gemm_bf3<4><<<dim3(QKVLD / 128, NTOK / 128), 256, SMEM3>>>(
        act3a, 3 * E_, w3, 3 * E_, 3 * E_, nullptr, 0, bqkv, nullptr, 0,
        nullptr, 0, 0, q3, k3, vf);
    // 3. V -> per-head transposed split v3
    split_vt<<<dim3(HD_ / 32, S_ / 32, B_ * H_), 256>>>(vf, v3);
    // 4. scores (HMMA split-3), causal block-skipped
    scores_mma<<<dim3(16, 16, B_ * H_), 256, SMEM3>>>(q3, k3, scores);
    // 5. softmax -> split W
    softmax_causal<<<dim3(S_, B_ * H_), 256>>>(scores, wa3);
    // 6. attn = W @ V (HMMA split-3) -> split act
    av_mma<<<dim3(16, B_ * H_), 256, SMEM3>>>(wa3, v3, act3a);
    // 7. Wo -> w3;  x2 = attn x Wo^T + bo + x
    split_wt<<<dim3(E_ / 32, E_ / 32), 256>>>(Wo, E_, E_, w3);
    gemm_bf3<3><<<dim3(E_ / 128, NTOK / 128), 256, SMEM3>>>(
        act3a, 3 * E_, w3, 3 * E_, 3 * E_, x2, E_, bo, x, E_,
        nullptr, 0, 0, nullptr, nullptr, nullptr);
    // 8. LN2 -> split activations
    ln_split<<<NTOK, 256>>>(x2, ln2_g, ln2_b, act3a);
    // 9. Wfc -> w3;  ff = gelu(h2 x Wfc^T + bfc) -> split
    split_wt<<<dim3(M_ / 32, E_ / 32), 256>>>(Wfc, E_, M_, w3);
    gemm_bf3<2><<<dim3(M_ / 128, NTOK / 128), 256, SMEM3>>>(
        act3a, 3 * E_, w3, 3 * E_, 3 * E_, nullptr, 0, bfc, nullptr, 0,
        act3b, 3 * M_, M_, nullptr, nullptr, nullptr);
    // 10. Wp -> w3;  out = ff x Wp^T + bp + x2
    split_wt<<<dim3(E_ / 32, M_ / 32), 256>>>(Wp, M_, E_, w3);
    gemm_bf3<3><<<dim3(E_ / 128, NTOK / 128), 256, SMEM3>>>(
        act3b, 3 * M_, w3, 3 * M_, 3 * M_, out, E_, bp, x2, E_,
        nullptr, 0, 0, nullptr, nullptr, nullptr);
}

// round 15
// speedup vs baseline: 1.1228x; 1.1228x over previous
#include <cuda_runtime.h>
#include <cuda_bf16.h>
#include <cstdint>
#include <math.h>

// Problem dims
#define B_    4
#define S_    2048
#define E_    2048
#define H_    16
#define HD_   128
#define M_    8192
#define NTOK  (B_ * S_)      // 8192
#define QKVLD (3 * E_)       // 6144

// ============================ PTX helpers (arch-generic, sm_80+) ============
__device__ __forceinline__ uint32_t smem_to_u32(const void* p) {
    uint32_t a;
    asm("{ .reg .u64 t; cvta.to.shared.u64 t, %1; cvt.u32.u64 %0, t; }" : "=r"(a) : "l"(p));
    return a;
}
__device__ __forceinline__ void cpa16(uint32_t s, const void* g) {
    asm volatile("cp.async.cg.shared.global [%0], [%1], 16;" :: "r"(s), "l"(g));
}
#define CPA_COMMIT()  asm volatile("cp.async.commit_group;" ::: "memory")
#define CPA_WAIT_1()  asm volatile("cp.async.wait_group 1;" ::: "memory")
#define CPA_WAIT_0()  asm volatile("cp.async.wait_group 0;" ::: "memory")

#define LDSM_X4(r0, r1, r2, r3, addr) \
    asm volatile("ldmatrix.sync.aligned.m8n8.x4.shared.b16 {%0,%1,%2,%3}, [%4];" \
        : "=r"(r0), "=r"(r1), "=r"(r2), "=r"(r3) : "r"(addr))
#define LDSM_X2(r0, r1, addr) \
    asm volatile("ldmatrix.sync.aligned.m8n8.x2.shared.b16 {%0,%1}, [%2];" \
        : "=r"(r0), "=r"(r1) : "r"(addr))
#define MMA_16816(c0, c1, c2, c3, a0, a1, a2, a3, b0, b1) \
    asm volatile("mma.sync.aligned.m16n8k16.row.col.f32.bf16.bf16.f32 " \
        "{%0,%1,%2,%3}, {%4,%5,%6,%7}, {%8,%9}, {%0,%1,%2,%3};" \
        : "+f"(c0), "+f"(c1), "+f"(c2), "+f"(c3) \
        : "r"(a0), "r"(a1), "r"(a2), "r"(a3), "r"(b0), "r"(b1))

// ============================ scratch =======================================
__device__ float          g_scores[(size_t)B_ * H_ * S_ * S_];  //   1 GB fp32
__device__ float          g_x2[(size_t)NTOK * E_];              //  64 MB fp32
__device__ float          g_vf[(size_t)NTOK * E_];              //  64 MB fp32 (V)
__device__ __nv_bfloat16  g_q3[(size_t)NTOK * H_ * 384];        // 100 MB (Q split)
__device__ __nv_bfloat16  g_k3[(size_t)NTOK * H_ * 384];        // 100 MB (K split)
__device__ __nv_bfloat16  g_v3[(size_t)B_ * H_ * HD_ * 3 * S_]; // 100 MB (V^T split)
__device__ __nv_bfloat16  g_wa3[(size_t)B_ * H_ * S_ * 3 * S_]; // 1.6 GB (softmax W split)
__device__ __nv_bfloat16  g_act3a[(size_t)NTOK * 3 * E_];       // 100 MB (split act)
__device__ __nv_bfloat16  g_act3b[(size_t)NTOK * 3 * M_];       // 402 MB (split ff)
__device__ __nv_bfloat16  g_w3[(size_t)50331648];               // 100 MB (split weights)

// ============================ math helpers ==================================
__device__ __forceinline__ float gelu_new(float x)
{
    float u = 0.7978845608028654f * (x + 0.044715f * x * x * x);
    return 0.5f * x * (1.0f + tanhf(u));
}

// A-side split: [hi | lo | hi] segments of width `seg` at base+col
__device__ __forceinline__ void store_split2(__nv_bfloat16* base, int col, int seg, float a, float b)
{
    __nv_bfloat16 ha = __float2bfloat16(a), hb = __float2bfloat16(b);
    __nv_bfloat16 la = __float2bfloat16(a - __bfloat162float(ha));
    __nv_bfloat16 lb = __float2bfloat16(b - __bfloat162float(hb));
    __nv_bfloat162 hh; hh.x = ha; hh.y = hb;
    __nv_bfloat162 ll; ll.x = la; ll.y = lb;
    *(__nv_bfloat162*)(base + col)           = hh;
    *(__nv_bfloat162*)(base + seg + col)     = ll;
    *(__nv_bfloat162*)(base + 2 * seg + col) = hh;
}
// B-side split: [hi | hi | lo]
__device__ __forceinline__ void store_split2b(__nv_bfloat16* base, int col, int seg, float a, float b)
{
    __nv_bfloat16 ha = __float2bfloat16(a), hb = __float2bfloat16(b);
    __nv_bfloat16 la = __float2bfloat16(a - __bfloat162float(ha));
    __nv_bfloat16 lb = __float2bfloat16(b - __bfloat162float(hb));
    __nv_bfloat162 hh; hh.x = ha; hh.y = hb;
    __nv_bfloat162 ll; ll.x = la; ll.y = lb;
    *(__nv_bfloat162*)(base + col)           = hh;
    *(__nv_bfloat162*)(base + seg + col)     = hh;
    *(__nv_bfloat162*)(base + 2 * seg + col) = ll;
}

// ---------------- LayerNorm -> split bf16 [hi|lo|hi], row stride 6144 -------
__global__ __launch_bounds__(256)
void ln_split(const float* __restrict__ x, const float* __restrict__ gam,
              const float* __restrict__ bet, __nv_bfloat16* __restrict__ out3)
{
    const int row = blockIdx.x;
    const int t = threadIdx.x;
    const float4* x4 = reinterpret_cast<const float4*>(x + (size_t)row * E_);
    float4 v0 = x4[t];
    float4 v1 = x4[t + 256];

    __shared__ float sh[256];
    float s = v0.x + v0.y + v0.z + v0.w + v1.x + v1.y + v1.z + v1.w;
    sh[t] = s;
    __syncthreads();
    #pragma unroll
    for (int o = 128; o > 0; o >>= 1) {
        if (t < o) sh[t] += sh[t + o];
        __syncthreads();
    }
    const float mu = sh[0] * (1.0f / (float)E_);
    __syncthreads();

    float d, sq = 0.f;
    d = v0.x - mu; sq += d * d;  d = v0.y - mu; sq += d * d;
    d = v0.z - mu; sq += d * d;  d = v0.w - mu; sq += d * d;
    d = v1.x - mu; sq += d * d;  d = v1.y - mu; sq += d * d;
    d = v1.z - mu; sq += d * d;  d = v1.w - mu; sq += d * d;
    sh[t] = sq;
    __syncthreads();
    #pragma unroll
    for (int o = 128; o > 0; o >>= 1) {
        if (t < o) sh[t] += sh[t + o];
        __syncthreads();
    }
    const float var = sh[0] * (1.0f / (float)E_);
    const float inv = rsqrtf(var + 1e-5f);

    const float4* g4 = reinterpret_cast<const float4*>(gam);
    const float4* b4 = reinterpret_cast<const float4*>(bet);
    float4 gg0 = g4[t], gg1 = g4[t + 256];
    float4 bb0 = b4[t], bb1 = b4[t + 256];

    float o0x = (v0.x - mu) * inv * gg0.x + bb0.x;
    float o0y = (v0.y - mu) * inv * gg0.y + bb0.y;
    float o0z = (v0.z - mu) * inv * gg0.z + bb0.z;
    float o0w = (v0.w - mu) * inv * gg0.w + bb0.w;
    float o1x = (v1.x - mu) * inv * gg1.x + bb1.x;
    float o1y = (v1.y - mu) * inv * gg1.y + bb1.y;
    float o1z = (v1.z - mu) * inv * gg1.z + bb1.z;
    float o1w = (v1.w - mu) * inv * gg1.w + bb1.w;

    __nv_bfloat16* o = out3 + (size_t)row * (3 * E_);
    store_split2(o, 4 * t,            E_, o0x, o0y);
    store_split2(o, 4 * t + 2,        E_, o0z, o0w);
    store_split2(o, 1024 + 4 * t,     E_, o1x, o1y);
    store_split2(o, 1024 + 4 * t + 2, E_, o1z, o1w);
}

// ---------------- weight split+transpose: W[K,N] fp32 -> out[N, 3K] bf16 ----
// segments [hi | hi | lo]
__global__ __launch_bounds__(256)
void split_wt(const float* __restrict__ W, int K, int N, __nv_bfloat16* __restrict__ out)
{
    __shared__ float tile[32][33];
    const int n0 = blockIdx.x * 32, k0 = blockIdx.y * 32;
    const int tx = threadIdx.x & 31, ty = threadIdx.x >> 5;  // ty 0..7
    #pragma unroll
    for (int i = 0; i < 4; i++)
        tile[ty + i * 8][tx] = W[(size_t)(k0 + ty + i * 8) * N + n0 + tx];
    __syncthreads();
    const size_t ld3 = (size_t)3 * K;
    #pragma unroll
    for (int i = 0; i < 4; i++) {
        int n = n0 + ty + i * 8;
        float v = tile[tx][ty + i * 8];
        __nv_bfloat16 hv = __float2bfloat16(v);
        __nv_bfloat16 lv = __float2bfloat16(v - __bfloat162float(hv));
        __nv_bfloat16* o = out + (size_t)n * ld3 + k0 + tx;
        o[0]     = hv;
        o[K]     = hv;
        o[2 * K] = lv;
    }
}

// ---------------- V split+transpose: per head, vf[s, h*128+d] -> v3[d, 3*2048]
__global__ __launch_bounds__(256)
void split_vt(const float* __restrict__ vf, __nv_bfloat16* __restrict__ v3)
{
    __shared__ float tile[32][33];
    const int z = blockIdx.z;                 // head index b*16+h
    const int b = z >> 4, h = z & 15;
    const int n0 = blockIdx.x * 32;           // d
    const int k0 = blockIdx.y * 32;           // s
    const int tx = threadIdx.x & 31, ty = threadIdx.x >> 5;
    const float* Wb = vf + ((size_t)b * S_) * E_ + h * HD_;
    #pragma unroll
    for (int i = 0; i < 4; i++)
        tile[ty + i * 8][tx] = Wb[(size_t)(k0 + ty + i * 8) * E_ + n0 + tx];
    __syncthreads();
    #pragma unroll
    for (int i = 0; i < 4; i++) {
        int n = n0 + ty + i * 8;
        float v = tile[tx][ty + i * 8];
        __nv_bfloat16 hv = __float2bfloat16(v);
        __nv_bfloat16 lv = __float2bfloat16(v - __bfloat162float(hv));
        __nv_bfloat16* o = v3 + ((size_t)z * HD_ + n) * (3 * S_) + k0 + tx;
        o[0]        = hv;
        o[S_]       = hv;
        o[2 * S_]   = lv;
    }
}

// ---------------- HMMA bf16 GEMM, BK=64, 2-stage (R13 ordering) --------------
// CTA 128x128, 8 warps of 64x32. wait -> sync -> compute -> sync -> prefetch.
// EPI: 2 = gelu(+bias) -> split bf16 ; 3 = +bias+res -> fp32 ; 4 = qkv special
#define BKC  64
#define PADK 72                      // smem row bf16 (64 data + 8 pad)
#define TSTG (128 * PADK * 2)        // 18432 B per tile stage
#define SMEM2 (4 * TSTG)             // 2 stages x (A + B) = 73728 B

#define ATT_SCALE 0.08838834764831845f

template<int EPI>
__global__ __launch_bounds__(256, 2)
void gemm_bf3(const __nv_bfloat16* __restrict__ A, int lda,
              const __nv_bfloat16* __restrict__ Bw, int ldb, int K,
              float* __restrict__ Cf, int ldc,
              const float* __restrict__ bias,
              const float* __restrict__ res, int ldres,
              __nv_bfloat16* __restrict__ Cs, int ldcs, int koff,
              __nv_bfloat16* __restrict__ q3, __nv_bfloat16* __restrict__ k3,
              float* __restrict__ vf)
{
    extern __shared__ char smem[];
    const uint32_t ASM = smem_to_u32(smem);       // 2 A stages
    const uint32_t BSM = ASM + 2 * TSTG;          // 2 B stages

    const int t = threadIdx.x;
    const int wid = t >> 5, lane = t & 31;
    const int wm = (wid >> 2) * 64;
    const int wn = (wid & 3) * 32;
    const int row0 = blockIdx.y * 128;
    const int col0 = blockIdx.x * 128;

    // loader mapping: 32 rows x 64 cols per pass, 4 passes per 128x64 tile
    const int gr = t >> 3;               // 0..31
    const int gc = (t & 7) * 8;          // bf16 col
    const __nv_bfloat16* Ag = A  + (size_t)(row0 + gr) * lda + gc;
    const __nv_bfloat16* Bg = Bw + (size_t)(col0 + gr) * ldb + gc;
    const size_t ldA32 = (size_t)32 * lda;
    const size_t ldB32 = (size_t)32 * ldb;
    const uint32_t ldo0 = (uint32_t)(gr * PADK + gc) * 2;

    float acc[4][4][4];
    #pragma unroll
    for (int i = 0; i < 4; i++)
        #pragma unroll
        for (int j = 0; j < 4; j++)
            #pragma unroll
            for (int q = 0; q < 4; q++) acc[i][j][q] = 0.f;

    const int nchunks = K / BKC;

    #pragma unroll
    for (int c = 0; c < 2; c++) {
        const int kc = c * BKC;
        #pragma unroll
        for (int s = 0; s < 4; s++) {
            const uint32_t so = ldo0 + (uint32_t)(32 * s * PADK) * 2;
            cpa16(ASM + c * TSTG + so, Ag + (size_t)s * ldA32 + kc);
            cpa16(BSM + c * TSTG + so, Bg + (size_t)s * ldB32 + kc);
        }
        CPA_COMMIT();
    }

    const int al = lane & 15;
    const uint32_t a_base = ASM + (uint32_t)((wm + (lane & 15)) * PADK + (lane >> 4) * 8) * 2;
    const uint32_t b_base = BSM + (uint32_t)((wn + (al & 7)) * PADK + (al >> 3) * 8) * 2;

    for (int c = 0; c < nchunks; c++) {
        if (c + 1 < nchunks) CPA_WAIT_1(); else CPA_WAIT_0();
        __syncthreads();

        const int p = c & 1;
        const uint32_t ab = a_base + p * TSTG;
        const uint32_t bb = b_base + p * TSTG;

        #pragma unroll
        for (int kk = 0; kk < 4; kk++) {
            uint32_t a[4][4], b[4][2];
            #pragma unroll
            for (int mt = 0; mt < 4; mt++)
                LDSM_X4(a[mt][0], a[mt][1], a[mt][2], a[mt][3],
                        ab + (mt * 16 * PADK + kk * 16) * 2);
            #pragma unroll
            for (int nt = 0; nt < 4; nt++)
                LDSM_X2(b[nt][0], b[nt][1],
                        bb + (nt * 8 * PADK + kk * 16) * 2);
            #pragma unroll
            for (int mt = 0; mt < 4; mt++)
                #pragma unroll
                for (int nt = 0; nt < 4; nt++)
                    MMA_16816(acc[mt][nt][0], acc[mt][nt][1], acc[mt][nt][2], acc[mt][nt][3],
                              a[mt][0], a[mt][1], a[mt][2], a[mt][3],
                              b[nt][0], b[nt][1]);
        }
        __syncthreads();

        if (c + 2 < nchunks) {
            const int kc = (c + 2) * BKC;
            #pragma unroll
            for (int s = 0; s < 4; s++) {
                const uint32_t so = ldo0 + (uint32_t)(32 * s * PADK) * 2;
                cpa16(ASM + p * TSTG + so, Ag + (size_t)s * ldA32 + kc);
                cpa16(BSM + p * TSTG + so, Bg + (size_t)s * ldB32 + kc);
            }
            CPA_COMMIT();
        }
    }

    // ---- epilogue ----
    const int er = lane >> 2;
    const int ec = (lane & 3) * 2;
    #pragma unroll
    for (int mt = 0; mt < 4; mt++) {
        #pragma unroll
        for (int nt = 0; nt < 4; nt++) {
            const int r  = row0 + wm + mt * 16 + er;
            const int ci = col0 + wn + nt * 8 + ec;
            float b0 = bias[ci], b1 = bias[ci + 1];
            float v0 = acc[mt][nt][0] + b0, v1 = acc[mt][nt][1] + b1;
            float v2 = acc[mt][nt][2] + b0, v3 = acc[mt][nt][3] + b1;
            if (EPI == 2) {
                __nv_bfloat16* base0 = Cs + (size_t)r * ldcs;
                __nv_bfloat16* base1 = Cs + (size_t)(r + 8) * ldcs;
                store_split2(base0, ci, koff, gelu_new(v0), gelu_new(v1));
                store_split2(base1, ci, koff, gelu_new(v2), gelu_new(v3));
            } else if (EPI == 3) {
                float2 r0 = *(const float2*)(res + (size_t)r * ldres + ci);
                float2 r1 = *(const float2*)(res + (size_t)(r + 8) * ldres + ci);
                v0 += r0.x; v1 += r0.y; v2 += r1.x; v3 += r1.y;
                float2 w0; w0.x = v0; w0.y = v1;
                float2 w1; w1.x = v2; w1.y = v3;
                *(float2*)(Cf + (size_t)r * ldc + ci)       = w0;
                *(float2*)(Cf + (size_t)(r + 8) * ldc + ci) = w1;
            } else {  // EPI == 4: qkv — q->q3 scaled split, k->k3 split, v->vf fp32
                if (ci < E_) {
                    const int h = ci >> 7, dd = ci & 127;
                    store_split2(q3 + (size_t)r * (H_ * 384) + h * 384, dd, HD_,
                                 v0 * ATT_SCALE, v1 * ATT_SCALE);
                    store_split2(q3 + (size_t)(r + 8) * (H_ * 384) + h * 384, dd, HD_,
                                 v2 * ATT_SCALE, v3 * ATT_SCALE);
                } else if (ci < 2 * E_) {
                    const int c2 = ci - E_;
                    const int h = c2 >> 7, dd = c2 & 127;
                    store_split2b(k3 + (size_t)r * (H_ * 384) + h * 384, dd, HD_, v0, v1);
                    store_split2b(k3 + (size_t)(r + 8) * (H_ * 384) + h * 384, dd, HD_, v2, v3);
                } else {
                    const int c2 = ci - 2 * E_;
                    float2 w0; w0.x = v0; w0.y = v1;
                    float2 w1; w1.x = v2; w1.y = v3;
                    *(float2*)(vf + (size_t)r * E_ + c2)       = w0;
                    *(float2*)(vf + (size_t)(r + 8) * E_ + c2) = w1;
                }
            }
        }
    }
}

// ---------------- scores = Qs @ Ks^T (HMMA, split-3, BK=64) ------------------
__global__ __launch_bounds__(256, 2)
void scores_mma(const __nv_bfloat16* __restrict__ q3, const __nv_bfloat16* __restrict__ k3,
                float* __restrict__ scores)
{
    const int bn = blockIdx.x, bm = blockIdx.y;
    if (bn > bm) return;
    const int z = blockIdx.z;
    const int b = z >> 4, h = z & 15;
    const int row0 = bm * 128, col0 = bn * 128;
    const int lda = H_ * 384;

    extern __shared__ char smem[];
    const uint32_t ASM = smem_to_u32(smem);
    const uint32_t BSM = ASM + 2 * TSTG;

    const int t = threadIdx.x;
    const int wid = t >> 5, lane = t & 31;
    const int wm = (wid >> 2) * 64;
    const int wn = (wid & 3) * 32;
    const int gr = t >> 3;
    const int gc = (t & 7) * 8;

    const __nv_bfloat16* Ag = q3 + (size_t)((b << 11) + row0 + gr) * lda + h * 384 + gc;
    const __nv_bfloat16* Bg = k3 + (size_t)((b << 11) + col0 + gr) * lda + h * 384 + gc;
    const size_t ld32 = (size_t)32 * lda;
    const uint32_t ldo0 = (uint32_t)(gr * PADK + gc) * 2;

    float acc[4][4][4];
    #pragma unroll
    for (int i = 0; i < 4; i++)
        #pragma unroll
        for (int j = 0; j < 4; j++)
            #pragma unroll
            for (int q = 0; q < 4; q++) acc[i][j][q] = 0.f;

    const int nchunks = 384 / BKC;   // 6

    #pragma unroll
    for (int c = 0; c < 2; c++) {
        const int kc = c * BKC;
        #pragma unroll
        for (int s = 0; s < 4; s++) {
            const uint32_t so = ldo0 + (uint32_t)(32 * s * PADK) * 2;
            cpa16(ASM + c * TSTG + so, Ag + (size_t)s * ld32 + kc);
            cpa16(BSM + c * TSTG + so, Bg + (size_t)s * ld32 + kc);
        }
        CPA_COMMIT();
    }

    const int al = lane & 15;
    const uint32_t a_base = ASM + (uint32_t)((wm + (lane & 15)) * PADK + (lane >> 4) * 8) * 2;
    const uint32_t b_base = BSM + (uint32_t)((wn + (al & 7)) * PADK + (al >> 3) * 8) * 2;

    for (int c = 0; c < nchunks; c++) {
        if (c + 1 < nchunks) CPA_WAIT_1(); else CPA_WAIT_0();
        __syncthreads();
        const int p = c & 1;
        const uint32_t ab = a_base + p * TSTG;
        const uint32_t bb = b_base + p * TSTG;
        #pragma unroll
        for (int kk = 0; kk < 4; kk++) {
            uint32_t a[4][4], bfr[4][2];
            #pragma unroll
            for (int mt = 0; mt < 4; mt++)
                LDSM_X4(a[mt][0], a[mt][1], a[mt][2], a[mt][3],
                        ab + (mt * 16 * PADK + kk * 16) * 2);
            #pragma unroll
            for (int nt = 0; nt < 4; nt++)
                LDSM_X2(bfr[nt][0], bfr[nt][1],
                        bb + (nt * 8 * PADK + kk * 16) * 2);
            #pragma unroll
            for (int mt = 0; mt < 4; mt++)
                #pragma unroll
                for (int nt = 0; nt < 4; nt++)
                    MMA_16816(acc[mt][nt][0], acc[mt][nt][1], acc[mt][nt][2], acc[mt][nt][3],
                              a[mt][0], a[mt][1], a[mt][2], a[mt][3],
                              bfr[nt][0], bfr[nt][1]);
        }
        __syncthreads();
        if (c + 2 < nchunks) {
            const int kc = (c + 2) * BKC;
            #pragma unroll
            for (int s = 0; s < 4; s++) {
                const uint32_t so = ldo0 + (uint32_t)(32 * s * PADK) * 2;
                cpa16(ASM + p * TSTG + so, Ag + (size_t)s * ld32 + kc);
                cpa16(BSM + p * TSTG + so, Bg + (size_t)s * ld32 + kc);
            }
            CPA_COMMIT();
        }
    }

    float* sbuf = scores + (size_t)z * S_ * S_;
    const int er = lane >> 2;
    const int ec = (lane & 3) * 2;
    #pragma unroll
    for (int mt = 0; mt < 4; mt++) {
        #pragma unroll
        for (int nt = 0; nt < 4; nt++) {
            const int r  = row0 + wm + mt * 16 + er;
            const int ci = col0 + wn + nt * 8 + ec;
            float2 w0; w0.x = acc[mt][nt][0]; w0.y = acc[mt][nt][1];
            float2 w1; w1.x = acc[mt][nt][2]; w1.y = acc[mt][nt][3];
            *(float2*)(sbuf + (size_t)r * S_ + ci)       = w0;
            *(float2*)(sbuf + (size_t)(r + 8) * S_ + ci) = w1;
        }
    }
}

// ---------------- causal softmax -> split bf16 W [hi|lo|hi] ------------------
__global__ __launch_bounds__(256)
void softmax_causal(const float* __restrict__ scores, __nv_bfloat16* __restrict__ wa3)
{
    const int q = blockIdx.x;
    const int z = blockIdx.y;
    const float* row = scores + (size_t)z * S_ * S_ + (size_t)q * S_;
    const int len = q + 1;
    const int kend = ((q >> 7) + 1) << 7;
    const int t = threadIdx.x;

    float r[8];
    float mx = -1e30f;
    #pragma unroll
    for (int i = 0; i < 8; i++) {
        const int k = t + i * 256;
        r[i] = (k < len) ? row[k] : -1e30f;
        mx = fmaxf(mx, r[i]);
    }
    __shared__ float sh[256];
    sh[t] = mx;
    __syncthreads();
    #pragma unroll
    for (int o = 128; o > 0; o >>= 1) {
        if (t < o) sh[t] = fmaxf(sh[t], sh[t + o]);
        __syncthreads();
    }
    mx = sh[0];
    __syncthreads();

    float sum = 0.f;
    #pragma unroll
    for (int i = 0; i < 8; i++) {
        const int k = t + i * 256;
        if (k < len) { r[i] = __expf(r[i] - mx); sum += r[i]; }
        else r[i] = 0.f;
    }
    sh[t] = sum;
    __syncthreads();
    #pragma unroll
    for (int o = 128; o > 0; o >>= 1) {
        if (t < o) sh[t] += sh[t + o];
        __syncthreads();
    }
    const float inv = 1.0f / sh[0];

    __nv_bfloat16* wrow = wa3 + ((size_t)z * S_ + q) * (3 * S_);
    #pragma unroll
    for (int i = 0; i < 8; i++) {
        const int k = t + i * 256;
        if (k < kend) {
            float w = (k < len) ? r[i] * inv : 0.f;
            __nv_bfloat16 hi = __float2bfloat16(w);
            __nv_bfloat16 lo = __float2bfloat16(w - __bfloat162float(hi));
            wrow[k]          = hi;
            wrow[S_ + k]     = lo;
            wrow[2 * S_ + k] = hi;
        }
    }
}

// ---------------- attn = W @ V (HMMA, split-3, BK=64) ------------------------
__global__ __launch_bounds__(256, 2)
void av_mma(const __nv_bfloat16* __restrict__ wa3, const __nv_bfloat16* __restrict__ v3,
            __nv_bfloat16* __restrict__ act3)
{
    const int qt = blockIdx.x;
    const int z = blockIdx.y;
    const int b = z >> 4, h = z & 15;
    const int row0 = qt * 128;
    const int Kend = (qt + 1) * 128;
    const int nchunks = 3 * Kend / BKC;

    extern __shared__ char smem[];
    const uint32_t ASM = smem_to_u32(smem);
    const uint32_t BSM = ASM + 2 * TSTG;

    const int t = threadIdx.x;
    const int wid = t >> 5, lane = t & 31;
    const int wm = (wid >> 2) * 64;
    const int wn = (wid & 3) * 32;
    const int gr = t >> 3;
    const int gc = (t & 7) * 8;

    const __nv_bfloat16* Ag = wa3 + ((size_t)z * S_ + row0 + gr) * (3 * S_) + gc;
    const __nv_bfloat16* Bg = v3 + ((size_t)z * HD_ + gr) * (3 * S_) + gc;
    const size_t ld32 = (size_t)32 * (3 * S_);
    const uint32_t ldo0 = (uint32_t)(gr * PADK + gc) * 2;

    float acc[4][4][4];
    #pragma unroll
    for (int i = 0; i < 4; i++)
        #pragma unroll
        for (int j = 0; j < 4; j++)
            #pragma unroll
            for (int q = 0; q < 4; q++) acc[i][j][q] = 0.f;

    // load cursor: chunk -> column offset seg*2048 + kin
    int lseg = 0, lkin = 0;

    #pragma unroll
    for (int c = 0; c < 2; c++) {
        const int off = lseg * S_ + lkin;
        #pragma unroll
        for (int s = 0; s < 4; s++) {
            const uint32_t so = ldo0 + (uint32_t)(32 * s * PADK) * 2;
            cpa16(ASM + c * TSTG + so, Ag + (size_t)s * ld32 + off);
            cpa16(BSM + c * TSTG + so, Bg + (size_t)s * ld32 + off);
        }
        CPA_COMMIT();
        lkin += BKC; if (lkin == Kend) { lkin = 0; lseg++; }
    }

    const int al = lane & 15;
    const uint32_t a_base = ASM + (uint32_t)((wm + (lane & 15)) * PADK + (lane >> 4) * 8) * 2;
    const uint32_t b_base = BSM + (uint32_t)((wn + (al & 7)) * PADK + (al >> 3) * 8) * 2;

    for (int c = 0; c < nchunks; c++) {
        if (c + 1 < nchunks) CPA_WAIT_1(); else CPA_WAIT_0();
        __syncthreads();
        const int p = c & 1;
        const uint32_t ab = a_base + p * TSTG;
        const uint32_t bb = b_base + p * TSTG;
        #pragma unroll
        for (int kk = 0; kk < 4; kk++) {
            uint32_t a[4][4], bfr[4][2];
            #pragma unroll
            for (int mt = 0; mt < 4; mt++)
                LDSM_X4(a[mt][0], a[mt][1], a[mt][2], a[mt][3],
                        ab + (mt * 16 * PADK + kk * 16) * 2);
            #pragma unroll
            for (int nt = 0; nt < 4; nt++)
                LDSM_X2(bfr[nt][0], bfr[nt][1],
                        bb + (nt * 8 * PADK + kk * 16) * 2);
            #pragma unroll
            for (int mt = 0; mt < 4; mt++)
                #pragma unroll
                for (int nt = 0; nt < 4; nt++)
                    MMA_16816(acc[mt][nt][0], acc[mt][nt][1], acc[mt][nt][2], acc[mt][nt][3],
                              a[mt][0], a[mt][1], a[mt][2], a[mt][3],
                              bfr[nt][0], bfr[nt][1]);
        }
        __syncthreads();
        if (c + 2 < nchunks) {
            const int off = lseg * S_ + lkin;
            #pragma unroll
            for (int s = 0; s < 4; s++) {
                const uint32_t so = ldo0 + (uint32_t)(32 * s * PADK) * 2;
                cpa16(ASM + p * TSTG + so, Ag + (size_t)s * ld32 + off);
                cpa16(BSM + p * TSTG + so, Bg + (size_t)s * ld32 + off);
            }
            CPA_COMMIT();
            lkin += BKC; if (lkin == Kend) { lkin = 0; lseg++; }
        }
    }

    // epilogue: write split activations for Wo GEMM
    const int er = lane >> 2;
    const int ec = (lane & 3) * 2;
    #pragma unroll
    for (int mt = 0; mt < 4; mt++) {
        #pragma unroll
        for (int nt = 0; nt < 4; nt++) {
            const int tok = (b << 11) + row0 + wm + mt * 16 + er;
            const int dd  = wn + nt * 8 + ec;       // 0..127
            __nv_bfloat16* op0 = act3 + (size_t)tok * (3 * E_) + h * HD_;
            __nv_bfloat16* op1 = act3 + (size_t)(tok + 8) * (3 * E_) + h * HD_;
            store_split2(op0, dd, E_, acc[mt][nt][0], acc[mt][nt][1]);
            store_split2(op1, dd, E_, acc[mt][nt][2], acc[mt][nt][3]);
        }
    }
}

// ---------------- launch -----------------------------------------------------
extern "C" void kernel_launch(void* const* d_in, const int* in_sizes, int n_in,
                              void* d_out, int out_size)
{
    const float* x     = (const float*)d_in[0];
    // d_in[1] = mask — causality handled directly
    const float* ln1_g = (const float*)d_in[2];
    const float* ln1_b = (const float*)d_in[3];
    const float* Wqkv  = (const float*)d_in[4];
    const float* bqkv  = (const float*)d_in[5];
    const float* Wo    = (const float*)d_in[6];
    const float* bo    = (const float*)d_in[7];
    const float* ln2_g = (const float*)d_in[8];
    const float* ln2_b = (const float*)d_in[9];
    const float* Wfc   = (const float*)d_in[10];
    const float* bfc   = (const float*)d_in[11];
    const float* Wp    = (const float*)d_in[12];
    const float* bp    = (const float*)d_in[13];
    float* out = (float*)d_out;

    float *scores, *x2, *vf;
    __nv_bfloat16 *act3a, *act3b, *w3, *q3, *k3, *v3, *wa3;
    cudaGetSymbolAddress((void**)&scores, g_scores);
    cudaGetSymbolAddress((void**)&x2, g_x2);
    cudaGetSymbolAddress((void**)&vf, g_vf);
    cudaGetSymbolAddress((void**)&act3a, g_act3a);
    cudaGetSymbolAddress((void**)&act3b, g_act3b);
    cudaGetSymbolAddress((void**)&w3, g_w3);
    cudaGetSymbolAddress((void**)&q3, g_q3);
    cudaGetSymbolAddress((void**)&k3, g_k3);
    cudaGetSymbolAddress((void**)&v3, g_v3);
    cudaGetSymbolAddress((void**)&wa3, g_wa3);

    cudaFuncSetAttribute(gemm_bf3<2>, cudaFuncAttributeMaxDynamicSharedMemorySize, SMEM2);
    cudaFuncSetAttribute(gemm_bf3<3>, cudaFuncAttributeMaxDynamicSharedMemorySize, SMEM2);
    cudaFuncSetAttribute(gemm_bf3<4>, cudaFuncAttributeMaxDynamicSharedMemorySize, SMEM2);
    cudaFuncSetAttribute(scores_mma, cudaFuncAttributeMaxDynamicSharedMemorySize, SMEM2);
    cudaFuncSetAttribute(av_mma, cudaFuncAttributeMaxDynamicSharedMemorySize, SMEM2);

    // 1. LN1 -> split activations [8192, 3*2048]
    ln_split<<<NTOK, 256>>>(x, ln1_g, ln1_b, act3a);
    // 2. Wqkv -> w3;  qkv GEMM -> q3 (scaled, split) / k3 (split) / vf (fp32)
    split_wt<<<dim3(QKVLD / 32, E_ / 32), 256>>>(Wqkv, E_, QKVLD, w3);
    gemm_bf3<4><<<dim3(QKVLD / 128, NTOK / 128), 256, SMEM2>>>(
        act3a, 3 * E_, w3, 3 * E_, 3 * E_, nullptr, 0, bqkv, nullptr, 0,
        nullptr, 0, 0, q3, k3, vf);
    // 3. V -> per-head transposed split v3
    split_vt<<<dim3(HD_ / 32, S_ / 32, B_ * H_), 256>>>(vf, v3);
    // 4. scores (HMMA split-3), causal block-skipped
    scores_mma<<<dim3(16, 16, B_ * H_), 256, SMEM2>>>(q3, k3, scores);
    // 5. softmax -> split W
    softmax_causal<<<dim3(S_, B_ * H_), 256>>>(scores, wa3);
    // 6. attn = W @ V (HMMA split-3) -> split act
    av_mma<<<dim3(16, B_ * H_), 256, SMEM2>>>(wa3, v3, act3a);
    // 7. Wo -> w3;  x2 = attn x Wo^T + bo + x
    split_wt<<<dim3(E_ / 32, E_ / 32), 256>>>(Wo, E_, E_, w3);
    gemm_bf3<3><<<dim3(E_ / 128, NTOK / 128), 256, SMEM2>>>(
        act3a, 3 * E_, w3, 3 * E_, 3 * E_, x2, E_, bo, x, E_,
        nullptr, 0, 0, nullptr, nullptr, nullptr);
    // 8. LN2 -> split activations
    ln_split<<<NTOK, 256>>>(x2, ln2_g, ln2_b, act3a);
    // 9. Wfc -> w3;  ff = gelu(h2 x Wfc^T + bfc) -> split
    split_wt<<<dim3(M_ / 32, E_ / 32), 256>>>(Wfc, E_, M_, w3);
    gemm_bf3<2><<<dim3(M_ / 128, NTOK / 128), 256, SMEM2>>>(
        act3a, 3 * E_, w3, 3 * E_, 3 * E_, nullptr, 0, bfc, nullptr, 0,
        act3b, 3 * M_, M_, nullptr, nullptr, nullptr);
    // 10. Wp -> w3;  out = ff x Wp^T + bp + x2
    split_wt<<<dim3(E_ / 32, M_ / 32), 256>>>(Wp, M_, E_, w3);
    gemm_bf3<3><<<dim3(E_ / 128, NTOK / 128), 256, SMEM2>>>(
        act3b, 3 * M_, w3, 3 * M_, 3 * M_, out, E_, bp, x2, E_,
        nullptr, 0, 0, nullptr, nullptr, nullptr);
}

// round 16
// speedup vs baseline: 1.1393x; 1.0147x over previous
#include <cuda_runtime.h>
#include <cuda_bf16.h>
#include <cstdint>
#include <math.h>

// Problem dims
#define B_    4
#define S_    2048
#define E_    2048
#define H_    16
#define HD_   128
#define M_    8192
#define NTOK  (B_ * S_)      // 8192
#define QKVLD (3 * E_)       // 6144

// ============================ PTX helpers (arch-generic, sm_80+) ============
__device__ __forceinline__ uint32_t smem_to_u32(const void* p) {
    uint32_t a;
    asm("{ .reg .u64 t; cvta.to.shared.u64 t, %1; cvt.u32.u64 %0, t; }" : "=r"(a) : "l"(p));
    return a;
}
__device__ __forceinline__ void cpa16(uint32_t s, const void* g) {
    asm volatile("cp.async.cg.shared.global [%0], [%1], 16;" :: "r"(s), "l"(g));
}
#define CPA_COMMIT()  asm volatile("cp.async.commit_group;" ::: "memory")
#define CPA_WAIT_1()  asm volatile("cp.async.wait_group 1;" ::: "memory")
#define CPA_WAIT_0()  asm volatile("cp.async.wait_group 0;" ::: "memory")

#define LDSM_X4(r0, r1, r2, r3, addr) \
    asm volatile("ldmatrix.sync.aligned.m8n8.x4.shared.b16 {%0,%1,%2,%3}, [%4];" \
        : "=r"(r0), "=r"(r1), "=r"(r2), "=r"(r3) : "r"(addr))
#define MMA_16816(c0, c1, c2, c3, a0, a1, a2, a3, b0, b1) \
    asm volatile("mma.sync.aligned.m16n8k16.row.col.f32.bf16.bf16.f32 " \
        "{%0,%1,%2,%3}, {%4,%5,%6,%7}, {%8,%9}, {%0,%1,%2,%3};" \
        : "+f"(c0), "+f"(c1), "+f"(c2), "+f"(c3) \
        : "r"(a0), "r"(a1), "r"(a2), "r"(a3), "r"(b0), "r"(b1))

// ============================ scratch =======================================
__device__ float          g_scores[(size_t)B_ * H_ * S_ * S_];  //   1 GB fp32
__device__ float          g_x2[(size_t)NTOK * E_];              //  64 MB fp32
__device__ float          g_vf[(size_t)NTOK * E_];              //  64 MB fp32 (V)
__device__ __nv_bfloat16  g_q3[(size_t)NTOK * H_ * 384];        // 100 MB (Q split)
__device__ __nv_bfloat16  g_k3[(size_t)NTOK * H_ * 384];        // 100 MB (K split)
__device__ __nv_bfloat16  g_v3[(size_t)B_ * H_ * HD_ * 3 * S_]; // 100 MB (V^T split)
__device__ __nv_bfloat16  g_wa3[(size_t)B_ * H_ * S_ * 3 * S_]; // 1.6 GB (softmax W split)
__device__ __nv_bfloat16  g_act3a[(size_t)NTOK * 3 * E_];       // 100 MB (split act)
__device__ __nv_bfloat16  g_act3b[(size_t)NTOK * 3 * M_];       // 402 MB (split ff)
__device__ __nv_bfloat16  g_w3[(size_t)50331648];               // 100 MB (split weights)

// ============================ math helpers ==================================
__device__ __forceinline__ float gelu_new(float x)
{
    float u = 0.7978845608028654f * (x + 0.044715f * x * x * x);
    return 0.5f * x * (1.0f + tanhf(u));
}

// A-side split: [hi | lo | hi] segments of width `seg` at base+col
__device__ __forceinline__ void store_split2(__nv_bfloat16* base, int col, int seg, float a, float b)
{
    __nv_bfloat16 ha = __float2bfloat16(a), hb = __float2bfloat16(b);
    __nv_bfloat16 la = __float2bfloat16(a - __bfloat162float(ha));
    __nv_bfloat16 lb = __float2bfloat16(b - __bfloat162float(hb));
    __nv_bfloat162 hh; hh.x = ha; hh.y = hb;
    __nv_bfloat162 ll; ll.x = la; ll.y = lb;
    *(__nv_bfloat162*)(base + col)           = hh;
    *(__nv_bfloat162*)(base + seg + col)     = ll;
    *(__nv_bfloat162*)(base + 2 * seg + col) = hh;
}
// B-side split: [hi | hi | lo]
__device__ __forceinline__ void store_split2b(__nv_bfloat16* base, int col, int seg, float a, float b)
{
    __nv_bfloat16 ha = __float2bfloat16(a), hb = __float2bfloat16(b);
    __nv_bfloat16 la = __float2bfloat16(a - __bfloat162float(ha));
    __nv_bfloat16 lb = __float2bfloat16(b - __bfloat162float(hb));
    __nv_bfloat162 hh; hh.x = ha; hh.y = hb;
    __nv_bfloat162 ll; ll.x = la; ll.y = lb;
    *(__nv_bfloat162*)(base + col)           = hh;
    *(__nv_bfloat162*)(base + seg + col)     = hh;
    *(__nv_bfloat162*)(base + 2 * seg + col) = ll;
}

// ---------------- LayerNorm -> split bf16 [hi|lo|hi], row stride 6144 -------
__global__ __launch_bounds__(256)
void ln_split(const float* __restrict__ x, const float* __restrict__ gam,
              const float* __restrict__ bet, __nv_bfloat16* __restrict__ out3)
{
    const int row = blockIdx.x;
    const int t = threadIdx.x;
    const float4* x4 = reinterpret_cast<const float4*>(x + (size_t)row * E_);
    float4 v0 = x4[t];
    float4 v1 = x4[t + 256];

    __shared__ float sh[256];
    float s = v0.x + v0.y + v0.z + v0.w + v1.x + v1.y + v1.z + v1.w;
    sh[t] = s;
    __syncthreads();
    #pragma unroll
    for (int o = 128; o > 0; o >>= 1) {
        if (t < o) sh[t] += sh[t + o];
        __syncthreads();
    }
    const float mu = sh[0] * (1.0f / (float)E_);
    __syncthreads();

    float d, sq = 0.f;
    d = v0.x - mu; sq += d * d;  d = v0.y - mu; sq += d * d;
    d = v0.z - mu; sq += d * d;  d = v0.w - mu; sq += d * d;
    d = v1.x - mu; sq += d * d;  d = v1.y - mu; sq += d * d;
    d = v1.z - mu; sq += d * d;  d = v1.w - mu; sq += d * d;
    sh[t] = sq;
    __syncthreads();
    #pragma unroll
    for (int o = 128; o > 0; o >>= 1) {
        if (t < o) sh[t] += sh[t + o];
        __syncthreads();
    }
    const float var = sh[0] * (1.0f / (float)E_);
    const float inv = rsqrtf(var + 1e-5f);

    const float4* g4 = reinterpret_cast<const float4*>(gam);
    const float4* b4 = reinterpret_cast<const float4*>(bet);
    float4 gg0 = g4[t], gg1 = g4[t + 256];
    float4 bb0 = b4[t], bb1 = b4[t + 256];

    float o0x = (v0.x - mu) * inv * gg0.x + bb0.x;
    float o0y = (v0.y - mu) * inv * gg0.y + bb0.y;
    float o0z = (v0.z - mu) * inv * gg0.z + bb0.z;
    float o0w = (v0.w - mu) * inv * gg0.w + bb0.w;
    float o1x = (v1.x - mu) * inv * gg1.x + bb1.x;
    float o1y = (v1.y - mu) * inv * gg1.y + bb1.y;
    float o1z = (v1.z - mu) * inv * gg1.z + bb1.z;
    float o1w = (v1.w - mu) * inv * gg1.w + bb1.w;

    __nv_bfloat16* o = out3 + (size_t)row * (3 * E_);
    store_split2(o, 4 * t,            E_, o0x, o0y);
    store_split2(o, 4 * t + 2,        E_, o0z, o0w);
    store_split2(o, 1024 + 4 * t,     E_, o1x, o1y);
    store_split2(o, 1024 + 4 * t + 2, E_, o1z, o1w);
}

// ---------------- weight split+transpose: W[K,N] fp32 -> out[N, 3K] bf16 ----
// segments [hi | hi | lo]
__global__ __launch_bounds__(256)
void split_wt(const float* __restrict__ W, int K, int N, __nv_bfloat16* __restrict__ out)
{
    __shared__ float tile[32][33];
    const int n0 = blockIdx.x * 32, k0 = blockIdx.y * 32;
    const int tx = threadIdx.x & 31, ty = threadIdx.x >> 5;  // ty 0..7
    #pragma unroll
    for (int i = 0; i < 4; i++)
        tile[ty + i * 8][tx] = W[(size_t)(k0 + ty + i * 8) * N + n0 + tx];
    __syncthreads();
    const size_t ld3 = (size_t)3 * K;
    #pragma unroll
    for (int i = 0; i < 4; i++) {
        int n = n0 + ty + i * 8;
        float v = tile[tx][ty + i * 8];
        __nv_bfloat16 hv = __float2bfloat16(v);
        __nv_bfloat16 lv = __float2bfloat16(v - __bfloat162float(hv));
        __nv_bfloat16* o = out + (size_t)n * ld3 + k0 + tx;
        o[0]     = hv;
        o[K]     = hv;
        o[2 * K] = lv;
    }
}

// ---------------- V split+transpose: per head, vf[s, h*128+d] -> v3[d, 3*2048]
__global__ __launch_bounds__(256)
void split_vt(const float* __restrict__ vf, __nv_bfloat16* __restrict__ v3)
{
    __shared__ float tile[32][33];
    const int z = blockIdx.z;                 // head index b*16+h
    const int b = z >> 4, h = z & 15;
    const int n0 = blockIdx.x * 32;           // d
    const int k0 = blockIdx.y * 32;           // s
    const int tx = threadIdx.x & 31, ty = threadIdx.x >> 5;
    const float* Wb = vf + ((size_t)b * S_) * E_ + h * HD_;
    #pragma unroll
    for (int i = 0; i < 4; i++)
        tile[ty + i * 8][tx] = Wb[(size_t)(k0 + ty + i * 8) * E_ + n0 + tx];
    __syncthreads();
    #pragma unroll
    for (int i = 0; i < 4; i++) {
        int n = n0 + ty + i * 8;
        float v = tile[tx][ty + i * 8];
        __nv_bfloat16 hv = __float2bfloat16(v);
        __nv_bfloat16 lv = __float2bfloat16(v - __bfloat162float(hv));
        __nv_bfloat16* o = v3 + ((size_t)z * HD_ + n) * (3 * S_) + k0 + tx;
        o[0]        = hv;
        o[S_]       = hv;
        o[2 * S_]   = lv;
    }
}

// ============ HMMA GEMM tiles: BK=96 (gemm/scores), BK=64 (av) ==============
#define BKG   96
#define PADKG 104                     // 96 data + 8 pad
#define TSTGG (128 * PADKG * 2)       // 26624 B per tile stage
#define SMEMG (4 * TSTGG)             // 106496 B

#define BKA   64
#define PADKA 72
#define TSTGA (128 * PADKA * 2)       // 18432 B
#define SMEMA (4 * TSTGA)             // 73728 B

#define ATT_SCALE 0.08838834764831845f

// ---------------- HMMA bf16 GEMM, BK=96, 2-stage (R13 ordering) --------------
// CTA 128x128, 8 warps of 64x32. wait -> sync -> compute -> sync -> prefetch.
// EPI: 2 = gelu(+bias) -> split bf16 ; 3 = +bias+res -> fp32 ; 4 = qkv special
template<int EPI>
__global__ __launch_bounds__(256, 2)
void gemm_bf3(const __nv_bfloat16* __restrict__ A, int lda,
              const __nv_bfloat16* __restrict__ Bw, int ldb, int K,
              float* __restrict__ Cf, int ldc,
              const float* __restrict__ bias,
              const float* __restrict__ res, int ldres,
              __nv_bfloat16* __restrict__ Cs, int ldcs, int koff,
              __nv_bfloat16* __restrict__ q3, __nv_bfloat16* __restrict__ k3,
              float* __restrict__ vf)
{
    extern __shared__ char smem[];
    const uint32_t ASM = smem_to_u32(smem);       // 2 A stages
    const uint32_t BSM = ASM + 2 * TSTGG;         // 2 B stages

    const int t = threadIdx.x;
    const int wid = t >> 5, lane = t & 31;
    const int wm = (wid >> 2) * 64;
    const int wn = (wid & 3) * 32;
    const int row0 = blockIdx.y * 128;
    const int col0 = blockIdx.x * 128;

    // loader: cols 0-63 via 4 passes of (t>>3, (t&7)*8); cols 64-95 via 2 passes of (t>>2, 64+(t&3)*8)
    const int gr0 = t >> 3;               // 0..31
    const int gc0 = (t & 7) * 8;
    const int gr1 = t >> 2;               // 0..63
    const int gc1 = 64 + (t & 3) * 8;
    const __nv_bfloat16* Ag0 = A  + (size_t)(row0 + gr0) * lda + gc0;
    const __nv_bfloat16* Bg0 = Bw + (size_t)(col0 + gr0) * ldb + gc0;
    const __nv_bfloat16* Ag1 = A  + (size_t)(row0 + gr1) * lda + gc1;
    const __nv_bfloat16* Bg1 = Bw + (size_t)(col0 + gr1) * ldb + gc1;
    const uint32_t so0 = (uint32_t)(gr0 * PADKG + gc0) * 2;
    const uint32_t so1 = (uint32_t)(gr1 * PADKG + gc1) * 2;

    float acc[4][4][4];
    #pragma unroll
    for (int i = 0; i < 4; i++)
        #pragma unroll
        for (int j = 0; j < 4; j++)
            #pragma unroll
            for (int q = 0; q < 4; q++) acc[i][j][q] = 0.f;

    const int nchunks = K / BKG;

    #pragma unroll
    for (int c = 0; c < 2; c++) {
        const int kc = c * BKG;
        #pragma unroll
        for (int s = 0; s < 4; s++) {
            const uint32_t so = so0 + (uint32_t)(32 * s * PADKG) * 2;
            cpa16(ASM + c * TSTGG + so, Ag0 + (size_t)(32 * s) * lda + kc);
            cpa16(BSM + c * TSTGG + so, Bg0 + (size_t)(32 * s) * ldb + kc);
        }
        #pragma unroll
        for (int s = 0; s < 2; s++) {
            const uint32_t so = so1 + (uint32_t)(64 * s * PADKG) * 2;
            cpa16(ASM + c * TSTGG + so, Ag1 + (size_t)(64 * s) * lda + kc);
            cpa16(BSM + c * TSTGG + so, Bg1 + (size_t)(64 * s) * ldb + kc);
        }
        CPA_COMMIT();
    }

    const uint32_t a_base = ASM + (uint32_t)((wm + (lane & 15)) * PADKG + (lane >> 4) * 8) * 2;
    const uint32_t b_base = BSM + (uint32_t)((wn + (lane & 7) + ((lane >> 4) << 3)) * PADKG
                                             + ((lane >> 3) & 1) * 8) * 2;

    for (int c = 0; c < nchunks; c++) {
        if (c + 1 < nchunks) CPA_WAIT_1(); else CPA_WAIT_0();
        __syncthreads();

        const int p = c & 1;
        const uint32_t ab = a_base + p * TSTGG;
        const uint32_t bb = b_base + p * TSTGG;

        #pragma unroll
        for (int kk = 0; kk < 6; kk++) {
            uint32_t a[4][4], b[4][2];
            #pragma unroll
            for (int mt = 0; mt < 4; mt++)
                LDSM_X4(a[mt][0], a[mt][1], a[mt][2], a[mt][3],
                        ab + (mt * 16 * PADKG + kk * 16) * 2);
            #pragma unroll
            for (int np = 0; np < 2; np++)
                LDSM_X4(b[2 * np][0], b[2 * np][1], b[2 * np + 1][0], b[2 * np + 1][1],
                        bb + (np * 16 * PADKG + kk * 16) * 2);
            #pragma unroll
            for (int mt = 0; mt < 4; mt++)
                #pragma unroll
                for (int nt = 0; nt < 4; nt++)
                    MMA_16816(acc[mt][nt][0], acc[mt][nt][1], acc[mt][nt][2], acc[mt][nt][3],
                              a[mt][0], a[mt][1], a[mt][2], a[mt][3],
                              b[nt][0], b[nt][1]);
        }
        __syncthreads();

        if (c + 2 < nchunks) {
            const int kc = (c + 2) * BKG;
            #pragma unroll
            for (int s = 0; s < 4; s++) {
                const uint32_t so = so0 + (uint32_t)(32 * s * PADKG) * 2;
                cpa16(ASM + p * TSTGG + so, Ag0 + (size_t)(32 * s) * lda + kc);
                cpa16(BSM + p * TSTGG + so, Bg0 + (size_t)(32 * s) * ldb + kc);
            }
            #pragma unroll
            for (int s = 0; s < 2; s++) {
                const uint32_t so = so1 + (uint32_t)(64 * s * PADKG) * 2;
                cpa16(ASM + p * TSTGG + so, Ag1 + (size_t)(64 * s) * lda + kc);
                cpa16(BSM + p * TSTGG + so, Bg1 + (size_t)(64 * s) * ldb + kc);
            }
            CPA_COMMIT();
        }
    }

    // ---- epilogue ----
    const int er = lane >> 2;
    const int ec = (lane & 3) * 2;
    #pragma unroll
    for (int mt = 0; mt < 4; mt++) {
        #pragma unroll
        for (int nt = 0; nt < 4; nt++) {
            const int r  = row0 + wm + mt * 16 + er;
            const int ci = col0 + wn + nt * 8 + ec;
            float b0 = bias[ci], b1 = bias[ci + 1];
            float v0 = acc[mt][nt][0] + b0, v1 = acc[mt][nt][1] + b1;
            float v2 = acc[mt][nt][2] + b0, v3 = acc[mt][nt][3] + b1;
            if (EPI == 2) {
                __nv_bfloat16* base0 = Cs + (size_t)r * ldcs;
                __nv_bfloat16* base1 = Cs + (size_t)(r + 8) * ldcs;
                store_split2(base0, ci, koff, gelu_new(v0), gelu_new(v1));
                store_split2(base1, ci, koff, gelu_new(v2), gelu_new(v3));
            } else if (EPI == 3) {
                float2 r0 = *(const float2*)(res + (size_t)r * ldres + ci);
                float2 r1 = *(const float2*)(res + (size_t)(r + 8) * ldres + ci);
                v0 += r0.x; v1 += r0.y; v2 += r1.x; v3 += r1.y;
                float2 w0; w0.x = v0; w0.y = v1;
                float2 w1; w1.x = v2; w1.y = v3;
                *(float2*)(Cf + (size_t)r * ldc + ci)       = w0;
                *(float2*)(Cf + (size_t)(r + 8) * ldc + ci) = w1;
            } else {  // EPI == 4: qkv — q->q3 scaled split, k->k3 split, v->vf fp32
                if (ci < E_) {
                    const int h = ci >> 7, dd = ci & 127;
                    store_split2(q3 + (size_t)r * (H_ * 384) + h * 384, dd, HD_,
                                 v0 * ATT_SCALE, v1 * ATT_SCALE);
                    store_split2(q3 + (size_t)(r + 8) * (H_ * 384) + h * 384, dd, HD_,
                                 v2 * ATT_SCALE, v3 * ATT_SCALE);
                } else if (ci < 2 * E_) {
                    const int c2 = ci - E_;
                    const int h = c2 >> 7, dd = c2 & 127;
                    store_split2b(k3 + (size_t)r * (H_ * 384) + h * 384, dd, HD_, v0, v1);
                    store_split2b(k3 + (size_t)(r + 8) * (H_ * 384) + h * 384, dd, HD_, v2, v3);
                } else {
                    const int c2 = ci - 2 * E_;
                    float2 w0; w0.x = v0; w0.y = v1;
                    float2 w1; w1.x = v2; w1.y = v3;
                    *(float2*)(vf + (size_t)r * E_ + c2)       = w0;
                    *(float2*)(vf + (size_t)(r + 8) * E_ + c2) = w1;
                }
            }
        }
    }
}

// ---------------- scores = Qs @ Ks^T (HMMA, split-3, BK=96) ------------------
__global__ __launch_bounds__(256, 2)
void scores_mma(const __nv_bfloat16* __restrict__ q3, const __nv_bfloat16* __restrict__ k3,
                float* __restrict__ scores)
{
    const int bn = blockIdx.x, bm = blockIdx.y;
    if (bn > bm) return;
    const int z = blockIdx.z;
    const int b = z >> 4, h = z & 15;
    const int row0 = bm * 128, col0 = bn * 128;
    const int lda = H_ * 384;

    extern __shared__ char smem[];
    const uint32_t ASM = smem_to_u32(smem);
    const uint32_t BSM = ASM + 2 * TSTGG;

    const int t = threadIdx.x;
    const int wid = t >> 5, lane = t & 31;
    const int wm = (wid >> 2) * 64;
    const int wn = (wid & 3) * 32;

    const int gr0 = t >> 3;
    const int gc0 = (t & 7) * 8;
    const int gr1 = t >> 2;
    const int gc1 = 64 + (t & 3) * 8;
    const __nv_bfloat16* Ag0 = q3 + (size_t)((b << 11) + row0 + gr0) * lda + h * 384 + gc0;
    const __nv_bfloat16* Bg0 = k3 + (size_t)((b << 11) + col0 + gr0) * lda + h * 384 + gc0;
    const __nv_bfloat16* Ag1 = q3 + (size_t)((b << 11) + row0 + gr1) * lda + h * 384 + gc1;
    const __nv_bfloat16* Bg1 = k3 + (size_t)((b << 11) + col0 + gr1) * lda + h * 384 + gc1;
    const uint32_t so0 = (uint32_t)(gr0 * PADKG + gc0) * 2;
    const uint32_t so1 = (uint32_t)(gr1 * PADKG + gc1) * 2;

    float acc[4][4][4];
    #pragma unroll
    for (int i = 0; i < 4; i++)
        #pragma unroll
        for (int j = 0; j < 4; j++)
            #pragma unroll
            for (int q = 0; q < 4; q++) acc[i][j][q] = 0.f;

    const int nchunks = 384 / BKG;   // 4

    #pragma unroll
    for (int c = 0; c < 2; c++) {
        const int kc = c * BKG;
        #pragma unroll
        for (int s = 0; s < 4; s++) {
            const uint32_t so = so0 + (uint32_t)(32 * s * PADKG) * 2;
            cpa16(ASM + c * TSTGG + so, Ag0 + (size_t)(32 * s) * lda + kc);
            cpa16(BSM + c * TSTGG + so, Bg0 + (size_t)(32 * s) * lda + kc);
        }
        #pragma unroll
        for (int s = 0; s < 2; s++) {
            const uint32_t so = so1 + (uint32_t)(64 * s * PADKG) * 2;
            cpa16(ASM + c * TSTGG + so, Ag1 + (size_t)(64 * s) * lda + kc);
            cpa16(BSM + c * TSTGG + so, Bg1 + (size_t)(64 * s) * lda + kc);
        }
        CPA_COMMIT();
    }

    const uint32_t a_base = ASM + (uint32_t)((wm + (lane & 15)) * PADKG + (lane >> 4) * 8) * 2;
    const uint32_t b_base = BSM + (uint32_t)((wn + (lane & 7) + ((lane >> 4) << 3)) * PADKG
                                             + ((lane >> 3) & 1) * 8) * 2;

    for (int c = 0; c < nchunks; c++) {
        if (c + 1 < nchunks) CPA_WAIT_1(); else CPA_WAIT_0();
        __syncthreads();
        const int p = c & 1;
        const uint32_t ab = a_base + p * TSTGG;
        const uint32_t bb = b_base + p * TSTGG;
        #pragma unroll
        for (int kk = 0; kk < 6; kk++) {
            uint32_t a[4][4], bfr[4][2];
            #pragma unroll
            for (int mt = 0; mt < 4; mt++)
                LDSM_X4(a[mt][0], a[mt][1], a[mt][2], a[mt][3],
                        ab + (mt * 16 * PADKG + kk * 16) * 2);
            #pragma unroll
            for (int np = 0; np < 2; np++)
                LDSM_X4(bfr[2 * np][0], bfr[2 * np][1], bfr[2 * np + 1][0], bfr[2 * np + 1][1],
                        bb + (np * 16 * PADKG + kk * 16) * 2);
            #pragma unroll
            for (int mt = 0; mt < 4; mt++)
                #pragma unroll
                for (int nt = 0; nt < 4; nt++)
                    MMA_16816(acc[mt][nt][0], acc[mt][nt][1], acc[mt][nt][2], acc[mt][nt][3],
                              a[mt][0], a[mt][1], a[mt][2], a[mt][3],
                              bfr[nt][0], bfr[nt][1]);
        }
        __syncthreads();
        if (c + 2 < nchunks) {
            const int kc = (c + 2) * BKG;
            #pragma unroll
            for (int s = 0; s < 4; s++) {
                const uint32_t so = so0 + (uint32_t)(32 * s * PADKG) * 2;
                cpa16(ASM + p * TSTGG + so, Ag0 + (size_t)(32 * s) * lda + kc);
                cpa16(BSM + p * TSTGG + so, Bg0 + (size_t)(32 * s) * lda + kc);
            }
            #pragma unroll
            for (int s = 0; s < 2; s++) {
                const uint32_t so = so1 + (uint32_t)(64 * s * PADKG) * 2;
                cpa16(ASM + p * TSTGG + so, Ag1 + (size_t)(64 * s) * lda + kc);
                cpa16(BSM + p * TSTGG + so, Bg1 + (size_t)(64 * s) * lda + kc);
            }
            CPA_COMMIT();
        }
    }

    float* sbuf = scores + (size_t)z * S_ * S_;
    const int er = lane >> 2;
    const int ec = (lane & 3) * 2;
    #pragma unroll
    for (int mt = 0; mt < 4; mt++) {
        #pragma unroll
        for (int nt = 0; nt < 4; nt++) {
            const int r  = row0 + wm + mt * 16 + er;
            const int ci = col0 + wn + nt * 8 + ec;
            float2 w0; w0.x = acc[mt][nt][0]; w0.y = acc[mt][nt][1];
            float2 w1; w1.x = acc[mt][nt][2]; w1.y = acc[mt][nt][3];
            *(float2*)(sbuf + (size_t)r * S_ + ci)       = w0;
            *(float2*)(sbuf + (size_t)(r + 8) * S_ + ci) = w1;
        }
    }
}

// ---------------- causal softmax -> split bf16 W [hi|lo|hi] ------------------
__global__ __launch_bounds__(256)
void softmax_causal(const float* __restrict__ scores, __nv_bfloat16* __restrict__ wa3)
{
    const int q = blockIdx.x;
    const int z = blockIdx.y;
    const float* row = scores + (size_t)z * S_ * S_ + (size_t)q * S_;
    const int len = q + 1;
    const int kend = ((q >> 7) + 1) << 7;
    const int t = threadIdx.x;

    float r[8];
    float mx = -1e30f;
    #pragma unroll
    for (int i = 0; i < 8; i++) {
        const int k = t + i * 256;
        r[i] = (k < len) ? row[k] : -1e30f;
        mx = fmaxf(mx, r[i]);
    }
    __shared__ float sh[256];
    sh[t] = mx;
    __syncthreads();
    #pragma unroll
    for (int o = 128; o > 0; o >>= 1) {
        if (t < o) sh[t] = fmaxf(sh[t], sh[t + o]);
        __syncthreads();
    }
    mx = sh[0];
    __syncthreads();

    float sum = 0.f;
    #pragma unroll
    for (int i = 0; i < 8; i++) {
        const int k = t + i * 256;
        if (k < len) { r[i] = __expf(r[i] - mx); sum += r[i]; }
        else r[i] = 0.f;
    }
    sh[t] = sum;
    __syncthreads();
    #pragma unroll
    for (int o = 128; o > 0; o >>= 1) {
        if (t < o) sh[t] += sh[t + o];
        __syncthreads();
    }
    const float inv = 1.0f / sh[0];

    __nv_bfloat16* wrow = wa3 + ((size_t)z * S_ + q) * (3 * S_);
    #pragma unroll
    for (int i = 0; i < 8; i++) {
        const int k = t + i * 256;
        if (k < kend) {
            float w = (k < len) ? r[i] * inv : 0.f;
            __nv_bfloat16 hi = __float2bfloat16(w);
            __nv_bfloat16 lo = __float2bfloat16(w - __bfloat162float(hi));
            wrow[k]          = hi;
            wrow[S_ + k]     = lo;
            wrow[2 * S_ + k] = hi;
        }
    }
}

// ---------------- attn = W @ V (HMMA, split-3, BK=64) ------------------------
__global__ __launch_bounds__(256, 2)
void av_mma(const __nv_bfloat16* __restrict__ wa3, const __nv_bfloat16* __restrict__ v3,
            __nv_bfloat16* __restrict__ act3)
{
    const int qt = blockIdx.x;
    const int z = blockIdx.y;
    const int b = z >> 4, h = z & 15;
    const int row0 = qt * 128;
    const int Kend = (qt + 1) * 128;
    const int nchunks = 3 * Kend / BKA;

    extern __shared__ char smem[];
    const uint32_t ASM = smem_to_u32(smem);
    const uint32_t BSM = ASM + 2 * TSTGA;

    const int t = threadIdx.x;
    const int wid = t >> 5, lane = t & 31;
    const int wm = (wid >> 2) * 64;
    const int wn = (wid & 3) * 32;
    const int gr = t >> 3;
    const int gc = (t & 7) * 8;

    const __nv_bfloat16* Ag = wa3 + ((size_t)z * S_ + row0 + gr) * (3 * S_) + gc;
    const __nv_bfloat16* Bg = v3 + ((size_t)z * HD_ + gr) * (3 * S_) + gc;
    const size_t ld32 = (size_t)32 * (3 * S_);
    const uint32_t ldo0 = (uint32_t)(gr * PADKA + gc) * 2;

    float acc[4][4][4];
    #pragma unroll
    for (int i = 0; i < 4; i++)
        #pragma unroll
        for (int j = 0; j < 4; j++)
            #pragma unroll
            for (int q = 0; q < 4; q++) acc[i][j][q] = 0.f;

    // load cursor: chunk -> column offset seg*2048 + kin
    int lseg = 0, lkin = 0;

    #pragma unroll
    for (int c = 0; c < 2; c++) {
        const int off = lseg * S_ + lkin;
        #pragma unroll
        for (int s = 0; s < 4; s++) {
            const uint32_t so = ldo0 + (uint32_t)(32 * s * PADKA) * 2;
            cpa16(ASM + c * TSTGA + so, Ag + (size_t)s * ld32 + off);
            cpa16(BSM + c * TSTGA + so, Bg + (size_t)s * ld32 + off);
        }
        CPA_COMMIT();
        lkin += BKA; if (lkin == Kend) { lkin = 0; lseg++; }
    }

    const uint32_t a_base = ASM + (uint32_t)((wm + (lane & 15)) * PADKA + (lane >> 4) * 8) * 2;
    const uint32_t b_base = BSM + (uint32_t)((wn + (lane & 7) + ((lane >> 4) << 3)) * PADKA
                                             + ((lane >> 3) & 1) * 8) * 2;

    for (int c = 0; c < nchunks; c++) {
        if (c + 1 < nchunks) CPA_WAIT_1(); else CPA_WAIT_0();
        __syncthreads();
        const int p = c & 1;
        const uint32_t ab = a_base + p * TSTGA;
        const uint32_t bb = b_base + p * TSTGA;
        #pragma unroll
        for (int kk = 0; kk < 4; kk++) {
            uint32_t a[4][4], bfr[4][2];
            #pragma unroll
            for (int mt = 0; mt < 4; mt++)
                LDSM_X4(a[mt][0], a[mt][1], a[mt][2], a[mt][3],
                        ab + (mt * 16 * PADKA + kk * 16) * 2);
            #pragma unroll
            for (int np = 0; np < 2; np++)
                LDSM_X4(bfr[2 * np][0], bfr[2 * np][1], bfr[2 * np + 1][0], bfr[2 * np + 1][1],
                        bb + (np * 16 * PADKA + kk * 16) * 2);
            #pragma unroll
            for (int mt = 0; mt < 4; mt++)
                #pragma unroll
                for (int nt = 0; nt < 4; nt++)
                    MMA_16816(acc[mt][nt][0], acc[mt][nt][1], acc[mt][nt][2], acc[mt][nt][3],
                              a[mt][0], a[mt][1], a[mt][2], a[mt][3],
                              bfr[nt][0], bfr[nt][1]);
        }
        __syncthreads();
        if (c + 2 < nchunks) {
            const int off = lseg * S_ + lkin;
            #pragma unroll
            for (int s = 0; s < 4; s++) {
                const uint32_t so = ldo0 + (uint32_t)(32 * s * PADKA) * 2;
                cpa16(ASM + p * TSTGA + so, Ag + (size_t)s * ld32 + off);
                cpa16(BSM + p * TSTGA + so, Bg + (size_t)s * ld32 + off);
            }
            CPA_COMMIT();
            lkin += BKA; if (lkin == Kend) { lkin = 0; lseg++; }
        }
    }

    // epilogue: write split activations for Wo GEMM
    const int er = lane >> 2;
    const int ec = (lane & 3) * 2;
    #pragma unroll
    for (int mt = 0; mt < 4; mt++) {
        #pragma unroll
        for (int nt = 0; nt < 4; nt++) {
            const int tok = (b << 11) + row0 + wm + mt * 16 + er;
            const int dd  = wn + nt * 8 + ec;       // 0..127
            __nv_bfloat16* op0 = act3 + (size_t)tok * (3 * E_) + h * HD_;
            __nv_bfloat16* op1 = act3 + (size_t)(tok + 8) * (3 * E_) + h * HD_;
            store_split2(op0, dd, E_, acc[mt][nt][0], acc[mt][nt][1]);
            store_split2(op1, dd, E_, acc[mt][nt][2], acc[mt][nt][3]);
        }
    }
}

// ---------------- launch -----------------------------------------------------
extern "C" void kernel_launch(void* const* d_in, const int* in_sizes, int n_in,
                              void* d_out, int out_size)
{
    const float* x     = (const float*)d_in[0];
    // d_in[1] = mask — causality handled directly
    const float* ln1_g = (const float*)d_in[2];
    const float* ln1_b = (const float*)d_in[3];
    const float* Wqkv  = (const float*)d_in[4];
    const float* bqkv  = (const float*)d_in[5];
    const float* Wo    = (const float*)d_in[6];
    const float* bo    = (const float*)d_in[7];
    const float* ln2_g = (const float*)d_in[8];
    const float* ln2_b = (const float*)d_in[9];
    const float* Wfc   = (const float*)d_in[10];
    const float* bfc   = (const float*)d_in[11];
    const float* Wp    = (const float*)d_in[12];
    const float* bp    = (const float*)d_in[13];
    float* out = (float*)d_out;

    float *scores, *x2, *vf;
    __nv_bfloat16 *act3a, *act3b, *w3, *q3, *k3, *v3, *wa3;
    cudaGetSymbolAddress((void**)&scores, g_scores);
    cudaGetSymbolAddress((void**)&x2, g_x2);
    cudaGetSymbolAddress((void**)&vf, g_vf);
    cudaGetSymbolAddress((void**)&act3a, g_act3a);
    cudaGetSymbolAddress((void**)&act3b, g_act3b);
    cudaGetSymbolAddress((void**)&w3, g_w3);
    cudaGetSymbolAddress((void**)&q3, g_q3);
    cudaGetSymbolAddress((void**)&k3, g_k3);
    cudaGetSymbolAddress((void**)&v3, g_v3);
    cudaGetSymbolAddress((void**)&wa3, g_wa3);

    cudaFuncSetAttribute(gemm_bf3<2>, cudaFuncAttributeMaxDynamicSharedMemorySize, SMEMG);
    cudaFuncSetAttribute(gemm_bf3<3>, cudaFuncAttributeMaxDynamicSharedMemorySize, SMEMG);
    cudaFuncSetAttribute(gemm_bf3<4>, cudaFuncAttributeMaxDynamicSharedMemorySize, SMEMG);
    cudaFuncSetAttribute(scores_mma, cudaFuncAttributeMaxDynamicSharedMemorySize, SMEMG);
    cudaFuncSetAttribute(av_mma, cudaFuncAttributeMaxDynamicSharedMemorySize, SMEMA);

    // 1. LN1 -> split activations [8192, 3*2048]
    ln_split<<<NTOK, 256>>>(x, ln1_g, ln1_b, act3a);
    // 2. Wqkv -> w3;  qkv GEMM -> q3 (scaled, split) / k3 (split) / vf (fp32)
    split_wt<<<dim3(QKVLD / 32, E_ / 32), 256>>>(Wqkv, E_, QKVLD, w3);
    gemm_bf3<4><<<dim3(QKVLD / 128, NTOK / 128), 256, SMEMG>>>(
        act3a, 3 * E_, w3, 3 * E_, 3 * E_, nullptr, 0, bqkv, nullptr, 0,
        nullptr, 0, 0, q3, k3, vf);
    // 3. V -> per-head transposed split v3
    split_vt<<<dim3(HD_ / 32, S_ / 32, B_ * H_), 256>>>(vf, v3);
    // 4. scores (HMMA split-3), causal block-skipped
    scores_mma<<<dim3(16, 16, B_ * H_), 256, SMEMG>>>(q3, k3, scores);
    // 5. softmax -> split W
    softmax_causal<<<dim3(S_, B_ * H_), 256>>>(scores, wa3);
    // 6. attn = W @ V (HMMA split-3) -> split act
    av_mma<<<dim3(16, B_ * H_), 256, SMEMA>>>(wa3, v3, act3a);
    // 7. Wo -> w3;  x2 = attn x Wo^T + bo + x
    split_wt<<<dim3(E_ / 32, E_ / 32), 256>>>(Wo, E_, E_, w3);
    gemm_bf3<3><<<dim3(E_ / 128, NTOK / 128), 256, SMEMG>>>(
        act3a, 3 * E_, w3, 3 * E_, 3 * E_, x2, E_, bo, x, E_,
        nullptr, 0, 0, nullptr, nullptr, nullptr);
    // 8. LN2 -> split activations
    ln_split<<<NTOK, 256>>>(x2, ln2_g, ln2_b, act3a);
    // 9. Wfc -> w3;  ff = gelu(h2 x Wfc^T + bfc) -> split
    split_wt<<<dim3(M_ / 32, E_ / 32), 256>>>(Wfc, E_, M_, w3);
    gemm_bf3<2><<<dim3(M_ / 128, NTOK / 128), 256, SMEMG>>>(
        act3a, 3 * E_, w3, 3 * E_, 3 * E_, nullptr, 0, bfc, nullptr, 0,
        act3b, 3 * M_, M_, nullptr, nullptr, nullptr);
    // 10. Wp -> w3;  out = ff x Wp^T + bp + x2
    split_wt<<<dim3(E_ / 32, M_ / 32), 256>>>(Wp, M_, E_, w3);
    gemm_bf3<3><<<dim3(E_ / 128, NTOK / 128), 256, SMEMG>>>(
        act3b, 3 * M_, w3, 3 * M_, 3 * M_, out, E_, bp, x2, E_,
        nullptr, 0, 0, nullptr, nullptr, nullptr);
}

// round 17
// speedup vs baseline: 1.1426x; 1.0029x over previous
#include <cuda_runtime.h>
#include <cuda_bf16.h>
#include <cstdint>
#include <math.h>

// Problem dims
#define B_    4
#define S_    2048
#define E_    2048
#define H_    16
#define HD_   128
#define M_    8192
#define NTOK  (B_ * S_)      // 8192
#define QKVLD (3 * E_)       // 6144

// ============================ PTX helpers (arch-generic, sm_80+) ============
__device__ __forceinline__ uint32_t smem_to_u32(const void* p) {
    uint32_t a;
    asm("{ .reg .u64 t; cvta.to.shared.u64 t, %1; cvt.u32.u64 %0, t; }" : "=r"(a) : "l"(p));
    return a;
}
__device__ __forceinline__ void cpa16(uint32_t s, const void* g) {
    asm volatile("cp.async.cg.shared.global [%0], [%1], 16;" :: "r"(s), "l"(g));
}
#define CPA_COMMIT()  asm volatile("cp.async.commit_group;" ::: "memory")
#define CPA_WAIT_1()  asm volatile("cp.async.wait_group 1;" ::: "memory")
#define CPA_WAIT_0()  asm volatile("cp.async.wait_group 0;" ::: "memory")

#define LDSM_X4(r0, r1, r2, r3, addr) \
    asm volatile("ldmatrix.sync.aligned.m8n8.x4.shared.b16 {%0,%1,%2,%3}, [%4];" \
        : "=r"(r0), "=r"(r1), "=r"(r2), "=r"(r3) : "r"(addr))
#define MMA_16816(c0, c1, c2, c3, a0, a1, a2, a3, b0, b1) \
    asm volatile("mma.sync.aligned.m16n8k16.row.col.f32.bf16.bf16.f32 " \
        "{%0,%1,%2,%3}, {%4,%5,%6,%7}, {%8,%9}, {%0,%1,%2,%3};" \
        : "+f"(c0), "+f"(c1), "+f"(c2), "+f"(c3) \
        : "r"(a0), "r"(a1), "r"(a2), "r"(a3), "r"(b0), "r"(b1))

// ============================ scratch =======================================
__device__ float          g_scores[(size_t)B_ * H_ * S_ * S_];  //   1 GB fp32
__device__ float          g_x2[(size_t)NTOK * E_];              //  64 MB fp32
__device__ float          g_vf[(size_t)NTOK * E_];              //  64 MB fp32 (V)
__device__ __nv_bfloat16  g_q3[(size_t)NTOK * H_ * 384];        // 100 MB (Q split)
__device__ __nv_bfloat16  g_k3[(size_t)NTOK * H_ * 384];        // 100 MB (K split)
__device__ __nv_bfloat16  g_v3[(size_t)B_ * H_ * HD_ * 3 * S_]; // 100 MB (V^T split)
__device__ __nv_bfloat16  g_wa3[(size_t)B_ * H_ * S_ * 3 * S_]; // 1.6 GB (softmax W split)
__device__ __nv_bfloat16  g_act3a[(size_t)NTOK * 3 * E_];       // 100 MB (split act)
__device__ __nv_bfloat16  g_act3b[(size_t)NTOK * 3 * M_];       // 402 MB (split ff)
__device__ __nv_bfloat16  g_w3[(size_t)50331648];               // 100 MB (split weights)

// ============================ math helpers ==================================
__device__ __forceinline__ float gelu_new(float x)
{
    float u = 0.7978845608028654f * (x + 0.044715f * x * x * x);
    return 0.5f * x * (1.0f + tanhf(u));
}

// A-side split: [hi | lo | hi] segments of width `seg` at base+col
__device__ __forceinline__ void store_split2(__nv_bfloat16* base, int col, int seg, float a, float b)
{
    __nv_bfloat16 ha = __float2bfloat16(a), hb = __float2bfloat16(b);
    __nv_bfloat16 la = __float2bfloat16(a - __bfloat162float(ha));
    __nv_bfloat16 lb = __float2bfloat16(b - __bfloat162float(hb));
    __nv_bfloat162 hh; hh.x = ha; hh.y = hb;
    __nv_bfloat162 ll; ll.x = la; ll.y = lb;
    *(__nv_bfloat162*)(base + col)           = hh;
    *(__nv_bfloat162*)(base + seg + col)     = ll;
    *(__nv_bfloat162*)(base + 2 * seg + col) = hh;
}
// B-side split: [hi | hi | lo]
__device__ __forceinline__ void store_split2b(__nv_bfloat16* base, int col, int seg, float a, float b)
{
    __nv_bfloat16 ha = __float2bfloat16(a), hb = __float2bfloat16(b);
    __nv_bfloat16 la = __float2bfloat16(a - __bfloat162float(ha));
    __nv_bfloat16 lb = __float2bfloat16(b - __bfloat162float(hb));
    __nv_bfloat162 hh; hh.x = ha; hh.y = hb;
    __nv_bfloat162 ll; ll.x = la; ll.y = lb;
    *(__nv_bfloat162*)(base + col)           = hh;
    *(__nv_bfloat162*)(base + seg + col)     = hh;
    *(__nv_bfloat162*)(base + 2 * seg + col) = ll;
}

// ---------------- LayerNorm -> split bf16 [hi|lo|hi], row stride 6144 -------
__global__ __launch_bounds__(256)
void ln_split(const float* __restrict__ x, const float* __restrict__ gam,
              const float* __restrict__ bet, __nv_bfloat16* __restrict__ out3)
{
    const int row = blockIdx.x;
    const int t = threadIdx.x;
    const float4* x4 = reinterpret_cast<const float4*>(x + (size_t)row * E_);
    float4 v0 = x4[t];
    float4 v1 = x4[t + 256];

    __shared__ float sh[256];
    float s = v0.x + v0.y + v0.z + v0.w + v1.x + v1.y + v1.z + v1.w;
    sh[t] = s;
    __syncthreads();
    #pragma unroll
    for (int o = 128; o > 0; o >>= 1) {
        if (t < o) sh[t] += sh[t + o];
        __syncthreads();
    }
    const float mu = sh[0] * (1.0f / (float)E_);
    __syncthreads();

    float d, sq = 0.f;
    d = v0.x - mu; sq += d * d;  d = v0.y - mu; sq += d * d;
    d = v0.z - mu; sq += d * d;  d = v0.w - mu; sq += d * d;
    d = v1.x - mu; sq += d * d;  d = v1.y - mu; sq += d * d;
    d = v1.z - mu; sq += d * d;  d = v1.w - mu; sq += d * d;
    sh[t] = sq;
    __syncthreads();
    #pragma unroll
    for (int o = 128; o > 0; o >>= 1) {
        if (t < o) sh[t] += sh[t + o];
        __syncthreads();
    }
    const float var = sh[0] * (1.0f / (float)E_);
    const float inv = rsqrtf(var + 1e-5f);

    const float4* g4 = reinterpret_cast<const float4*>(gam);
    const float4* b4 = reinterpret_cast<const float4*>(bet);
    float4 gg0 = g4[t], gg1 = g4[t + 256];
    float4 bb0 = b4[t], bb1 = b4[t + 256];

    float o0x = (v0.x - mu) * inv * gg0.x + bb0.x;
    float o0y = (v0.y - mu) * inv * gg0.y + bb0.y;
    float o0z = (v0.z - mu) * inv * gg0.z + bb0.z;
    float o0w = (v0.w - mu) * inv * gg0.w + bb0.w;
    float o1x = (v1.x - mu) * inv * gg1.x + bb1.x;
    float o1y = (v1.y - mu) * inv * gg1.y + bb1.y;
    float o1z = (v1.z - mu) * inv * gg1.z + bb1.z;
    float o1w = (v1.w - mu) * inv * gg1.w + bb1.w;

    __nv_bfloat16* o = out3 + (size_t)row * (3 * E_);
    store_split2(o, 4 * t,            E_, o0x, o0y);
    store_split2(o, 4 * t + 2,        E_, o0z, o0w);
    store_split2(o, 1024 + 4 * t,     E_, o1x, o1y);
    store_split2(o, 1024 + 4 * t + 2, E_, o1z, o1w);
}

// ---------------- weight split+transpose: W[K,N] fp32 -> out[N, 3K] bf16 ----
// segments [hi | hi | lo]
__global__ __launch_bounds__(256)
void split_wt(const float* __restrict__ W, int K, int N, __nv_bfloat16* __restrict__ out)
{
    __shared__ float tile[32][33];
    const int n0 = blockIdx.x * 32, k0 = blockIdx.y * 32;
    const int tx = threadIdx.x & 31, ty = threadIdx.x >> 5;  // ty 0..7
    #pragma unroll
    for (int i = 0; i < 4; i++)
        tile[ty + i * 8][tx] = W[(size_t)(k0 + ty + i * 8) * N + n0 + tx];
    __syncthreads();
    const size_t ld3 = (size_t)3 * K;
    #pragma unroll
    for (int i = 0; i < 4; i++) {
        int n = n0 + ty + i * 8;
        float v = tile[tx][ty + i * 8];
        __nv_bfloat16 hv = __float2bfloat16(v);
        __nv_bfloat16 lv = __float2bfloat16(v - __bfloat162float(hv));
        __nv_bfloat16* o = out + (size_t)n * ld3 + k0 + tx;
        o[0]     = hv;
        o[K]     = hv;
        o[2 * K] = lv;
    }
}

// ---------------- V split+transpose: per head, vf[s, h*128+d] -> v3[d, 3*2048]
__global__ __launch_bounds__(256)
void split_vt(const float* __restrict__ vf, __nv_bfloat16* __restrict__ v3)
{
    __shared__ float tile[32][33];
    const int z = blockIdx.z;                 // head index b*16+h
    const int b = z >> 4, h = z & 15;
    const int n0 = blockIdx.x * 32;           // d
    const int k0 = blockIdx.y * 32;           // s
    const int tx = threadIdx.x & 31, ty = threadIdx.x >> 5;
    const float* Wb = vf + ((size_t)b * S_) * E_ + h * HD_;
    #pragma unroll
    for (int i = 0; i < 4; i++)
        tile[ty + i * 8][tx] = Wb[(size_t)(k0 + ty + i * 8) * E_ + n0 + tx];
    __syncthreads();
    #pragma unroll
    for (int i = 0; i < 4; i++) {
        int n = n0 + ty + i * 8;
        float v = tile[tx][ty + i * 8];
        __nv_bfloat16 hv = __float2bfloat16(v);
        __nv_bfloat16 lv = __float2bfloat16(v - __bfloat162float(hv));
        __nv_bfloat16* o = v3 + ((size_t)z * HD_ + n) * (3 * S_) + k0 + tx;
        o[0]        = hv;
        o[S_]       = hv;
        o[2 * S_]   = lv;
    }
}

// ============ HMMA GEMM tiles: BK=96 (gemm/scores), BK=64 (av) ==============
#define BKG   96
#define PADKG 104                     // 96 data + 8 pad
#define TSTGG (128 * PADKG * 2)       // 26624 B per tile stage
#define SMEMG (4 * TSTGG)             // 106496 B

#define BKA   64
#define PADKA 72
#define TSTGA (128 * PADKA * 2)       // 18432 B
#define SMEMA (4 * TSTGA)             // 73728 B

#define ATT_SCALE 0.08838834764831845f

// ---------------- HMMA bf16 GEMM, BK=96, 2-stage (R13 ordering) --------------
// CTA 128x128, 8 warps of 64x32. wait -> sync -> compute -> sync -> prefetch.
// Grouped tile rasterization (GROUP=8 M-tiles per panel) for L2 locality.
// EPI: 2 = gelu(+bias) -> split bf16 ; 3 = +bias+res -> fp32 ; 4 = qkv special
template<int EPI>
__global__ __launch_bounds__(256, 2)
void gemm_bf3(const __nv_bfloat16* __restrict__ A, int lda,
              const __nv_bfloat16* __restrict__ Bw, int ldb, int K,
              float* __restrict__ Cf, int ldc,
              const float* __restrict__ bias,
              const float* __restrict__ res, int ldres,
              __nv_bfloat16* __restrict__ Cs, int ldcs, int koff,
              __nv_bfloat16* __restrict__ q3, __nv_bfloat16* __restrict__ k3,
              float* __restrict__ vf)
{
    extern __shared__ char smem[];
    const uint32_t ASM = smem_to_u32(smem);       // 2 A stages
    const uint32_t BSM = ASM + 2 * TSTGG;         // 2 B stages

    const int t = threadIdx.x;
    const int wid = t >> 5, lane = t & 31;
    const int wm = (wid >> 2) * 64;
    const int wn = (wid & 3) * 32;

    // ---- grouped rasterization: panels of GROUP M-tiles, column-major in-panel
    const int nbn = gridDim.x, nbm = gridDim.y;
    const int pid = blockIdx.y * nbn + blockIdx.x;
    const int GROUP = 8;
    const int npg = GROUP * nbn;
    const int gid = pid / npg;
    const int fm = gid * GROUP;
    const int gsz = min(nbm - fm, GROUP);
    const int pm = fm + (pid % npg) % gsz;
    const int pn = (pid % npg) / gsz;
    const int row0 = pm * 128;
    const int col0 = pn * 128;

    // loader: cols 0-63 via 4 passes of (t>>3, (t&7)*8); cols 64-95 via 2 passes of (t>>2, 64+(t&3)*8)
    const int gr0 = t >> 3;               // 0..31
    const int gc0 = (t & 7) * 8;
    const int gr1 = t >> 2;               // 0..63
    const int gc1 = 64 + (t & 3) * 8;
    const __nv_bfloat16* Ag0 = A  + (size_t)(row0 + gr0) * lda + gc0;
    const __nv_bfloat16* Bg0 = Bw + (size_t)(col0 + gr0) * ldb + gc0;
    const __nv_bfloat16* Ag1 = A  + (size_t)(row0 + gr1) * lda + gc1;
    const __nv_bfloat16* Bg1 = Bw + (size_t)(col0 + gr1) * ldb + gc1;
    const uint32_t so0 = (uint32_t)(gr0 * PADKG + gc0) * 2;
    const uint32_t so1 = (uint32_t)(gr1 * PADKG + gc1) * 2;

    float acc[4][4][4];
    #pragma unroll
    for (int i = 0; i < 4; i++)
        #pragma unroll
        for (int j = 0; j < 4; j++)
            #pragma unroll
            for (int q = 0; q < 4; q++) acc[i][j][q] = 0.f;

    const int nchunks = K / BKG;

    #pragma unroll
    for (int c = 0; c < 2; c++) {
        const int kc = c * BKG;
        #pragma unroll
        for (int s = 0; s < 4; s++) {
            const uint32_t so = so0 + (uint32_t)(32 * s * PADKG) * 2;
            cpa16(ASM + c * TSTGG + so, Ag0 + (size_t)(32 * s) * lda + kc);
            cpa16(BSM + c * TSTGG + so, Bg0 + (size_t)(32 * s) * ldb + kc);
        }
        #pragma unroll
        for (int s = 0; s < 2; s++) {
            const uint32_t so = so1 + (uint32_t)(64 * s * PADKG) * 2;
            cpa16(ASM + c * TSTGG + so, Ag1 + (size_t)(64 * s) * lda + kc);
            cpa16(BSM + c * TSTGG + so, Bg1 + (size_t)(64 * s) * ldb + kc);
        }
        CPA_COMMIT();
    }

    const uint32_t a_base = ASM + (uint32_t)((wm + (lane & 15)) * PADKG + (lane >> 4) * 8) * 2;
    const uint32_t b_base = BSM + (uint32_t)((wn + (lane & 7) + ((lane >> 4) << 3)) * PADKG
                                             + ((lane >> 3) & 1) * 8) * 2;

    for (int c = 0; c < nchunks; c++) {
        if (c + 1 < nchunks) CPA_WAIT_1(); else CPA_WAIT_0();
        __syncthreads();

        const int p = c & 1;
        const uint32_t ab = a_base + p * TSTGG;
        const uint32_t bb = b_base + p * TSTGG;

        #pragma unroll
        for (int kk = 0; kk < 6; kk++) {
            uint32_t a[4][4], b[4][2];
            #pragma unroll
            for (int mt = 0; mt < 4; mt++)
                LDSM_X4(a[mt][0], a[mt][1], a[mt][2], a[mt][3],
                        ab + (mt * 16 * PADKG + kk * 16) * 2);
            #pragma unroll
            for (int np = 0; np < 2; np++)
                LDSM_X4(b[2 * np][0], b[2 * np][1], b[2 * np + 1][0], b[2 * np + 1][1],
                        bb + (np * 16 * PADKG + kk * 16) * 2);
            #pragma unroll
            for (int mt = 0; mt < 4; mt++)
                #pragma unroll
                for (int nt = 0; nt < 4; nt++)
                    MMA_16816(acc[mt][nt][0], acc[mt][nt][1], acc[mt][nt][2], acc[mt][nt][3],
                              a[mt][0], a[mt][1], a[mt][2], a[mt][3],
                              b[nt][0], b[nt][1]);
        }
        __syncthreads();

        if (c + 2 < nchunks) {
            const int kc = (c + 2) * BKG;
            #pragma unroll
            for (int s = 0; s < 4; s++) {
                const uint32_t so = so0 + (uint32_t)(32 * s * PADKG) * 2;
                cpa16(ASM + p * TSTGG + so, Ag0 + (size_t)(32 * s) * lda + kc);
                cpa16(BSM + p * TSTGG + so, Bg0 + (size_t)(32 * s) * ldb + kc);
            }
            #pragma unroll
            for (int s = 0; s < 2; s++) {
                const uint32_t so = so1 + (uint32_t)(64 * s * PADKG) * 2;
                cpa16(ASM + p * TSTGG + so, Ag1 + (size_t)(64 * s) * lda + kc);
                cpa16(BSM + p * TSTGG + so, Bg1 + (size_t)(64 * s) * ldb + kc);
            }
            CPA_COMMIT();
        }
    }

    // ---- epilogue ----
    const int er = lane >> 2;
    const int ec = (lane & 3) * 2;
    #pragma unroll
    for (int mt = 0; mt < 4; mt++) {
        #pragma unroll
        for (int nt = 0; nt < 4; nt++) {
            const int r  = row0 + wm + mt * 16 + er;
            const int ci = col0 + wn + nt * 8 + ec;
            float b0 = bias[ci], b1 = bias[ci + 1];
            float v0 = acc[mt][nt][0] + b0, v1 = acc[mt][nt][1] + b1;
            float v2 = acc[mt][nt][2] + b0, v3 = acc[mt][nt][3] + b1;
            if (EPI == 2) {
                __nv_bfloat16* base0 = Cs + (size_t)r * ldcs;
                __nv_bfloat16* base1 = Cs + (size_t)(r + 8) * ldcs;
                store_split2(base0, ci, koff, gelu_new(v0), gelu_new(v1));
                store_split2(base1, ci, koff, gelu_new(v2), gelu_new(v3));
            } else if (EPI == 3) {
                float2 r0 = *(const float2*)(res + (size_t)r * ldres + ci);
                float2 r1 = *(const float2*)(res + (size_t)(r + 8) * ldres + ci);
                v0 += r0.x; v1 += r0.y; v2 += r1.x; v3 += r1.y;
                float2 w0; w0.x = v0; w0.y = v1;
                float2 w1; w1.x = v2; w1.y = v3;
                *(float2*)(Cf + (size_t)r * ldc + ci)       = w0;
                *(float2*)(Cf + (size_t)(r + 8) * ldc + ci) = w1;
            } else {  // EPI == 4: qkv — q->q3 scaled split, k->k3 split, v->vf fp32
                if (ci < E_) {
                    const int h = ci >> 7, dd = ci & 127;
                    store_split2(q3 + (size_t)r * (H_ * 384) + h * 384, dd, HD_,
                                 v0 * ATT_SCALE, v1 * ATT_SCALE);
                    store_split2(q3 + (size_t)(r + 8) * (H_ * 384) + h * 384, dd, HD_,
                                 v2 * ATT_SCALE, v3 * ATT_SCALE);
                } else if (ci < 2 * E_) {
                    const int c2 = ci - E_;
                    const int h = c2 >> 7, dd = c2 & 127;
                    store_split2b(k3 + (size_t)r * (H_ * 384) + h * 384, dd, HD_, v0, v1);
                    store_split2b(k3 + (size_t)(r + 8) * (H_ * 384) + h * 384, dd, HD_, v2, v3);
                } else {
                    const int c2 = ci - 2 * E_;
                    float2 w0; w0.x = v0; w0.y = v1;
                    float2 w1; w1.x = v2; w1.y = v3;
                    *(float2*)(vf + (size_t)r * E_ + c2)       = w0;
                    *(float2*)(vf + (size_t)(r + 8) * E_ + c2) = w1;
                }
            }
        }
    }
}

// ---------------- scores = Qs @ Ks^T (HMMA, split-3, BK=96) ------------------
__global__ __launch_bounds__(256, 2)
void scores_mma(const __nv_bfloat16* __restrict__ q3, const __nv_bfloat16* __restrict__ k3,
                float* __restrict__ scores)
{
    const int bn = blockIdx.x, bm = blockIdx.y;
    if (bn > bm) return;
    const int z = blockIdx.z;
    const int b = z >> 4, h = z & 15;
    const int row0 = bm * 128, col0 = bn * 128;
    const int lda = H_ * 384;

    extern __shared__ char smem[];
    const uint32_t ASM = smem_to_u32(smem);
    const uint32_t BSM = ASM + 2 * TSTGG;

    const int t = threadIdx.x;
    const int wid = t >> 5, lane = t & 31;
    const int wm = (wid >> 2) * 64;
    const int wn = (wid & 3) * 32;

    const int gr0 = t >> 3;
    const int gc0 = (t & 7) * 8;
    const int gr1 = t >> 2;
    const int gc1 = 64 + (t & 3) * 8;
    const __nv_bfloat16* Ag0 = q3 + (size_t)((b << 11) + row0 + gr0) * lda + h * 384 + gc0;
    const __nv_bfloat16* Bg0 = k3 + (size_t)((b << 11) + col0 + gr0) * lda + h * 384 + gc0;
    const __nv_bfloat16* Ag1 = q3 + (size_t)((b << 11) + row0 + gr1) * lda + h * 384 + gc1;
    const __nv_bfloat16* Bg1 = k3 + (size_t)((b << 11) + col0 + gr1) * lda + h * 384 + gc1;
    const uint32_t so0 = (uint32_t)(gr0 * PADKG + gc0) * 2;
    const uint32_t so1 = (uint32_t)(gr1 * PADKG + gc1) * 2;

    float acc[4][4][4];
    #pragma unroll
    for (int i = 0; i < 4; i++)
        #pragma unroll
        for (int j = 0; j < 4; j++)
            #pragma unroll
            for (int q = 0; q < 4; q++) acc[i][j][q] = 0.f;

    const int nchunks = 384 / BKG;   // 4

    #pragma unroll
    for (int c = 0; c < 2; c++) {
        const int kc = c * BKG;
        #pragma unroll
        for (int s = 0; s < 4; s++) {
            const uint32_t so = so0 + (uint32_t)(32 * s * PADKG) * 2;
            cpa16(ASM + c * TSTGG + so, Ag0 + (size_t)(32 * s) * lda + kc);
            cpa16(BSM + c * TSTGG + so, Bg0 + (size_t)(32 * s) * lda + kc);
        }
        #pragma unroll
        for (int s = 0; s < 2; s++) {
            const uint32_t so = so1 + (uint32_t)(64 * s * PADKG) * 2;
            cpa16(ASM + c * TSTGG + so, Ag1 + (size_t)(64 * s) * lda + kc);
            cpa16(BSM + c * TSTGG + so, Bg1 + (size_t)(64 * s) * lda + kc);
        }
        CPA_COMMIT();
    }

    const uint32_t a_base = ASM + (uint32_t)((wm + (lane & 15)) * PADKG + (lane >> 4) * 8) * 2;
    const uint32_t b_base = BSM + (uint32_t)((wn + (lane & 7) + ((lane >> 4) << 3)) * PADKG
                                             + ((lane >> 3) & 1) * 8) * 2;

    for (int c = 0; c < nchunks; c++) {
        if (c + 1 < nchunks) CPA_WAIT_1(); else CPA_WAIT_0();
        __syncthreads();
        const int p = c & 1;
        const uint32_t ab = a_base + p * TSTGG;
        const uint32_t bb = b_base + p * TSTGG;
        #pragma unroll
        for (int kk = 0; kk < 6; kk++) {
            uint32_t a[4][4], bfr[4][2];
            #pragma unroll
            for (int mt = 0; mt < 4; mt++)
                LDSM_X4(a[mt][0], a[mt][1], a[mt][2], a[mt][3],
                        ab + (mt * 16 * PADKG + kk * 16) * 2);
            #pragma unroll
            for (int np = 0; np < 2; np++)
                LDSM_X4(bfr[2 * np][0], bfr[2 * np][1], bfr[2 * np + 1][0], bfr[2 * np + 1][1],
                        bb + (np * 16 * PADKG + kk * 16) * 2);
            #pragma unroll
            for (int mt = 0; mt < 4; mt++)
                #pragma unroll
                for (int nt = 0; nt < 4; nt++)
                    MMA_16816(acc[mt][nt][0], acc[mt][nt][1], acc[mt][nt][2], acc[mt][nt][3],
                              a[mt][0], a[mt][1], a[mt][2], a[mt][3],
                              bfr[nt][0], bfr[nt][1]);
        }
        __syncthreads();
        if (c + 2 < nchunks) {
            const int kc = (c + 2) * BKG;
            #pragma unroll
            for (int s = 0; s < 4; s++) {
                const uint32_t so = so0 + (uint32_t)(32 * s * PADKG) * 2;
                cpa16(ASM + p * TSTGG + so, Ag0 + (size_t)(32 * s) * lda + kc);
                cpa16(BSM + p * TSTGG + so, Bg0 + (size_t)(32 * s) * lda + kc);
            }
            #pragma unroll
            for (int s = 0; s < 2; s++) {
                const uint32_t so = so1 + (uint32_t)(64 * s * PADKG) * 2;
                cpa16(ASM + p * TSTGG + so, Ag1 + (size_t)(64 * s) * lda + kc);
                cpa16(BSM + p * TSTGG + so, Bg1 + (size_t)(64 * s) * lda + kc);
            }
            CPA_COMMIT();
        }
    }

    float* sbuf = scores + (size_t)z * S_ * S_;
    const int er = lane >> 2;
    const int ec = (lane & 3) * 2;
    #pragma unroll
    for (int mt = 0; mt < 4; mt++) {
        #pragma unroll
        for (int nt = 0; nt < 4; nt++) {
            const int r  = row0 + wm + mt * 16 + er;
            const int ci = col0 + wn + nt * 8 + ec;
            float2 w0; w0.x = acc[mt][nt][0]; w0.y = acc[mt][nt][1];
            float2 w1; w1.x = acc[mt][nt][2]; w1.y = acc[mt][nt][3];
            *(float2*)(sbuf + (size_t)r * S_ + ci)       = w0;
            *(float2*)(sbuf + (size_t)(r + 8) * S_ + ci) = w1;
        }
    }
}

// ---------------- causal softmax -> split bf16 W [hi|lo|hi] ------------------
__global__ __launch_bounds__(256)
void softmax_causal(const float* __restrict__ scores, __nv_bfloat16* __restrict__ wa3)
{
    const int q = blockIdx.x;
    const int z = blockIdx.y;
    const float* row = scores + (size_t)z * S_ * S_ + (size_t)q * S_;
    const int len = q + 1;
    const int kend = ((q >> 7) + 1) << 7;
    const int t = threadIdx.x;

    float r[8];
    float mx = -1e30f;
    #pragma unroll
    for (int i = 0; i < 8; i++) {
        const int k = t + i * 256;
        r[i] = (k < len) ? row[k] : -1e30f;
        mx = fmaxf(mx, r[i]);
    }
    __shared__ float sh[256];
    sh[t] = mx;
    __syncthreads();
    #pragma unroll
    for (int o = 128; o > 0; o >>= 1) {
        if (t < o) sh[t] = fmaxf(sh[t], sh[t + o]);
        __syncthreads();
    }
    mx = sh[0];
    __syncthreads();

    float sum = 0.f;
    #pragma unroll
    for (int i = 0; i < 8; i++) {
        const int k = t + i * 256;
        if (k < len) { r[i] = __expf(r[i] - mx); sum += r[i]; }
        else r[i] = 0.f;
    }
    sh[t] = sum;
    __syncthreads();
    #pragma unroll
    for (int o = 128; o > 0; o >>= 1) {
        if (t < o) sh[t] += sh[t + o];
        __syncthreads();
    }
    const float inv = 1.0f / sh[0];

    __nv_bfloat16* wrow = wa3 + ((size_t)z * S_ + q) * (3 * S_);
    #pragma unroll
    for (int i = 0; i < 8; i++) {
        const int k = t + i * 256;
        if (k < kend) {
            float w = (k < len) ? r[i] * inv : 0.f;
            __nv_bfloat16 hi = __float2bfloat16(w);
            __nv_bfloat16 lo = __float2bfloat16(w - __bfloat162float(hi));
            wrow[k]          = hi;
            wrow[S_ + k]     = lo;
            wrow[2 * S_ + k] = hi;
        }
    }
}

// ---------------- attn = W @ V (HMMA, split-3, BK=64) ------------------------
__global__ __launch_bounds__(256, 2)
void av_mma(const __nv_bfloat16* __restrict__ wa3, const __nv_bfloat16* __restrict__ v3,
            __nv_bfloat16* __restrict__ act3)
{
    const int qt = blockIdx.x;
    const int z = blockIdx.y;
    const int b = z >> 4, h = z & 15;
    const int row0 = qt * 128;
    const int Kend = (qt + 1) * 128;
    const int nchunks = 3 * Kend / BKA;

    extern __shared__ char smem[];
    const uint32_t ASM = smem_to_u32(smem);
    const uint32_t BSM = ASM + 2 * TSTGA;

    const int t = threadIdx.x;
    const int wid = t >> 5, lane = t & 31;
    const int wm = (wid >> 2) * 64;
    const int wn = (wid & 3) * 32;
    const int gr = t >> 3;
    const int gc = (t & 7) * 8;

    const __nv_bfloat16* Ag = wa3 + ((size_t)z * S_ + row0 + gr) * (3 * S_) + gc;
    const __nv_bfloat16* Bg = v3 + ((size_t)z * HD_ + gr) * (3 * S_) + gc;
    const size_t ld32 = (size_t)32 * (3 * S_);
    const uint32_t ldo0 = (uint32_t)(gr * PADKA + gc) * 2;

    float acc[4][4][4];
    #pragma unroll
    for (int i = 0; i < 4; i++)
        #pragma unroll
        for (int j = 0; j < 4; j++)
            #pragma unroll
            for (int q = 0; q < 4; q++) acc[i][j][q] = 0.f;

    // load cursor: chunk -> column offset seg*2048 + kin
    int lseg = 0, lkin = 0;

    #pragma unroll
    for (int c = 0; c < 2; c++) {
        const int off = lseg * S_ + lkin;
        #pragma unroll
        for (int s = 0; s < 4; s++) {
            const uint32_t so = ldo0 + (uint32_t)(32 * s * PADKA) * 2;
            cpa16(ASM + c * TSTGA + so, Ag + (size_t)s * ld32 + off);
            cpa16(BSM + c * TSTGA + so, Bg + (size_t)s * ld32 + off);
        }
        CPA_COMMIT();
        lkin += BKA; if (lkin == Kend) { lkin = 0; lseg++; }
    }

    const uint32_t a_base = ASM + (uint32_t)((wm + (lane & 15)) * PADKA + (lane >> 4) * 8) * 2;
    const uint32_t b_base = BSM + (uint32_t)((wn + (lane & 7) + ((lane >> 4) << 3)) * PADKA
                                             + ((lane >> 3) & 1) * 8) * 2;

    for (int c = 0; c < nchunks; c++) {
        if (c + 1 < nchunks) CPA_WAIT_1(); else CPA_WAIT_0();
        __syncthreads();
        const int p = c & 1;
        const uint32_t ab = a_base + p * TSTGA;
        const uint32_t bb = b_base + p * TSTGA;
        #pragma unroll
        for (int kk = 0; kk < 4; kk++) {
            uint32_t a[4][4], bfr[4][2];
            #pragma unroll
            for (int mt = 0; mt < 4; mt++)
                LDSM_X4(a[mt][0], a[mt][1], a[mt][2], a[mt][3],
                        ab + (mt * 16 * PADKA + kk * 16) * 2);
            #pragma unroll
            for (int np = 0; np < 2; np++)
                LDSM_X4(bfr[2 * np][0], bfr[2 * np][1], bfr[2 * np + 1][0], bfr[2 * np + 1][1],
                        bb + (np * 16 * PADKA + kk * 16) * 2);
            #pragma unroll
            for (int mt = 0; mt < 4; mt++)
                #pragma unroll
                for (int nt = 0; nt < 4; nt++)
                    MMA_16816(acc[mt][nt][0], acc[mt][nt][1], acc[mt][nt][2], acc[mt][nt][3],
                              a[mt][0], a[mt][1], a[mt][2], a[mt][3],
                              bfr[nt][0], bfr[nt][1]);
        }
        __syncthreads();
        if (c + 2 < nchunks) {
            const int off = lseg * S_ + lkin;
            #pragma unroll
            for (int s = 0; s < 4; s++) {
                const uint32_t so = ldo0 + (uint32_t)(32 * s * PADKA) * 2;
                cpa16(ASM + p * TSTGA + so, Ag + (size_t)s * ld32 + off);
                cpa16(BSM + p * TSTGA + so, Bg + (size_t)s * ld32 + off);
            }
            CPA_COMMIT();
            lkin += BKA; if (lkin == Kend) { lkin = 0; lseg++; }
        }
    }

    // epilogue: write split activations for Wo GEMM
    const int er = lane >> 2;
    const int ec = (lane & 3) * 2;
    #pragma unroll
    for (int mt = 0; mt < 4; mt++) {
        #pragma unroll
        for (int nt = 0; nt < 4; nt++) {
            const int tok = (b << 11) + row0 + wm + mt * 16 + er;
            const int dd  = wn + nt * 8 + ec;       // 0..127
            __nv_bfloat16* op0 = act3 + (size_t)tok * (3 * E_) + h * HD_;
            __nv_bfloat16* op1 = act3 + (size_t)(tok + 8) * (3 * E_) + h * HD_;
            store_split2(op0, dd, E_, acc[mt][nt][0], acc[mt][nt][1]);
            store_split2(op1, dd, E_, acc[mt][nt][2], acc[mt][nt][3]);
        }
    }
}

// ---------------- launch -----------------------------------------------------
extern "C" void kernel_launch(void* const* d_in, const int* in_sizes, int n_in,
                              void* d_out, int out_size)
{
    const float* x     = (const float*)d_in[0];
    // d_in[1] = mask — causality handled directly
    const float* ln1_g = (const float*)d_in[2];
    const float* ln1_b = (const float*)d_in[3];
    const float* Wqkv  = (const float*)d_in[4];
    const float* bqkv  = (const float*)d_in[5];
    const float* Wo    = (const float*)d_in[6];
    const float* bo    = (const float*)d_in[7];
    const float* ln2_g = (const float*)d_in[8];
    const float* ln2_b = (const float*)d_in[9];
    const float* Wfc   = (const float*)d_in[10];
    const float* bfc   = (const float*)d_in[11];
    const float* Wp    = (const float*)d_in[12];
    const float* bp    = (const float*)d_in[13];
    float* out = (float*)d_out;

    float *scores, *x2, *vf;
    __nv_bfloat16 *act3a, *act3b, *w3, *q3, *k3, *v3, *wa3;
    cudaGetSymbolAddress((void**)&scores, g_scores);
    cudaGetSymbolAddress((void**)&x2, g_x2);
    cudaGetSymbolAddress((void**)&vf, g_vf);
    cudaGetSymbolAddress((void**)&act3a, g_act3a);
    cudaGetSymbolAddress((void**)&act3b, g_act3b);
    cudaGetSymbolAddress((void**)&w3, g_w3);
    cudaGetSymbolAddress((void**)&q3, g_q3);
    cudaGetSymbolAddress((void**)&k3, g_k3);
    cudaGetSymbolAddress((void**)&v3, g_v3);
    cudaGetSymbolAddress((void**)&wa3, g_wa3);

    cudaFuncSetAttribute(gemm_bf3<2>, cudaFuncAttributeMaxDynamicSharedMemorySize, SMEMG);
    cudaFuncSetAttribute(gemm_bf3<3>, cudaFuncAttributeMaxDynamicSharedMemorySize, SMEMG);
    cudaFuncSetAttribute(gemm_bf3<4>, cudaFuncAttributeMaxDynamicSharedMemorySize, SMEMG);
    cudaFuncSetAttribute(scores_mma, cudaFuncAttributeMaxDynamicSharedMemorySize, SMEMG);
    cudaFuncSetAttribute(av_mma, cudaFuncAttributeMaxDynamicSharedMemorySize, SMEMA);

    // 1. LN1 -> split activations [8192, 3*2048]
    ln_split<<<NTOK, 256>>>(x, ln1_g, ln1_b, act3a);
    // 2. Wqkv -> w3;  qkv GEMM -> q3 (scaled, split) / k3 (split) / vf (fp32)
    split_wt<<<dim3(QKVLD / 32, E_ / 32), 256>>>(Wqkv, E_, QKVLD, w3);
    gemm_bf3<4><<<dim3(QKVLD / 128, NTOK / 128), 256, SMEMG>>>(
        act3a, 3 * E_, w3, 3 * E_, 3 * E_, nullptr, 0, bqkv, nullptr, 0,
        nullptr, 0, 0, q3, k3, vf);
    // 3. V -> per-head transposed split v3
    split_vt<<<dim3(HD_ / 32, S_ / 32, B_ * H_), 256>>>(vf, v3);
    // 4. scores (HMMA split-3), causal block-skipped
    scores_mma<<<dim3(16, 16, B_ * H_), 256, SMEMG>>>(q3, k3, scores);
    // 5. softmax -> split W
    softmax_causal<<<dim3(S_, B_ * H_), 256>>>(scores, wa3);
    // 6. attn = W @ V (HMMA split-3) -> split act
    av_mma<<<dim3(16, B_ * H_), 256, SMEMA>>>(wa3, v3, act3a);
    // 7. Wo -> w3;  x2 = attn x Wo^T + bo + x
    split_wt<<<dim3(E_ / 32, E_ / 32), 256>>>(Wo, E_, E_, w3);
    gemm_bf3<3><<<dim3(E_ / 128, NTOK / 128), 256, SMEMG>>>(
        act3a, 3 * E_, w3, 3 * E_, 3 * E_, x2, E_, bo, x, E_,
        nullptr, 0, 0, nullptr, nullptr, nullptr);
    // 8. LN2 -> split activations
    ln_split<<<NTOK, 256>>>(x2, ln2_g, ln2_b, act3a);
    // 9. Wfc -> w3;  ff = gelu(h2 x Wfc^T + bfc) -> split
    split_wt<<<dim3(M_ / 32, E_ / 32), 256>>>(Wfc, E_, M_, w3);
    gemm_bf3<2><<<dim3(M_ / 128, NTOK / 128), 256, SMEMG>>>(
        act3a, 3 * E_, w3, 3 * E_, 3 * E_, nullptr, 0, bfc, nullptr, 0,
        act3b, 3 * M_, M_, nullptr, nullptr, nullptr);
    // 10. Wp -> w3;  out = ff x Wp^T + bp + x2
    split_wt<<<dim3(E_ / 32, M_ / 32), 256>>>(Wp, M_, E_, w3);
    gemm_bf3<3><<<dim3(E_ / 128, NTOK / 128), 256, SMEMG>>>(
        act3b, 3 * M_, w3, 3 * M_, 3 * M_, out, E_, bp, x2, E_,
        nullptr, 0, 0, nullptr, nullptr, nullptr);
}